// round 12
// baseline (speedup 1.0000x reference)
#include <cuda_runtime.h>
#include <cuda_fp16.h>
#include <cstdint>

#define Bc  64
#define Mc  512
#define Hc  1024
#define NHc 8
#define HDc 128
#define EPSc 1e-5f

typedef __half f16;

#define BMH ((size_t)Bc*Mc*Hc)
#define BMM ((size_t)Bc*Mc*Mc)

// ---------------------------------------------------------------------------
// Scratch (static device globals — allocation-free)
// ---------------------------------------------------------------------------
__device__ float g_mw, g_mb;
__device__ f16 g_xah[BMM];
__device__ f16 g_h1[BMH];
__device__ float g_xreg[BMH];
__device__ f16 g_xnh[BMH];
__device__ f16 g_qkv[(size_t)Bc*Mc*3*Hc];         // [B*M, 3072] = q|k|v
__device__ f16 g_vth[BMH];                        // [B*NH, 128, 512]
__device__ f16 g_ch[BMH];
// fp16 weights
__device__ f16 g_w1t[(size_t)Hc*Mc];              // [N,K]
__device__ f16 g_w2t[(size_t)Hc*Hc];              // [N,K]
__device__ f16 g_wqkv[(size_t)3*Hc*Hc];           // [3072, 1024]
__device__ f16 g_wo16[(size_t)Hc*Hc];             // wo row-major (untransposed!)
__device__ f16 g_wpt[(size_t)Hc*Hc];              // [N,K]
__device__ f16 g_wopT[(size_t)Hc*Hc];             // (wo@wp)^T in [N,K]
__device__ float g_bqkv[3*Hc];
__device__ float g_bop[Hc];                       // bo@wp + bp

// ---------------------------------------------------------------------------
// PTX helpers (baseline PTX only — no tcgen05 on compute_103)
// ---------------------------------------------------------------------------
__device__ __forceinline__ uint32_t smem_u32(const void* p) {
    uint32_t a;
    asm("{ .reg .u64 t; cvta.to.shared.u64 t, %1; cvt.u32.u64 %0, t; }"
        : "=r"(a) : "l"(p));
    return a;
}

// pack two fp32 -> u32 {hi:f16(hi), lo:f16(lo)}
__device__ __forceinline__ uint32_t f2h2(float lo, float hi) {
    uint32_t r;
    asm("cvt.rn.f16x2.f32 %0, %1, %2;" : "=r"(r) : "f"(hi), "f"(lo));
    return r;
}

__device__ __forceinline__ void cp_async16(uint32_t saddr, const void* gaddr) {
    asm volatile("cp.async.cg.shared.global [%0], [%1], 16;\n"
                 :: "r"(saddr), "l"(gaddr));
}
__device__ __forceinline__ void cp_commit() {
    asm volatile("cp.async.commit_group;\n" ::: "memory");
}
template<int N>
__device__ __forceinline__ void cp_wait() {
    asm volatile("cp.async.wait_group %0;\n" :: "n"(N) : "memory");
}

__device__ __forceinline__ void ldsm4(uint32_t& r0, uint32_t& r1, uint32_t& r2, uint32_t& r3,
                                      uint32_t addr) {
    asm volatile("ldmatrix.sync.aligned.m8n8.x4.shared.b16 {%0,%1,%2,%3}, [%4];"
                 : "=r"(r0), "=r"(r1), "=r"(r2), "=r"(r3) : "r"(addr));
}

__device__ __forceinline__ void mma16816(float* c, const uint32_t* a, uint32_t b0, uint32_t b1) {
    asm volatile("mma.sync.aligned.m16n8k16.row.col.f32.f16.f16.f32 "
                 "{%0,%1,%2,%3}, {%4,%5,%6,%7}, {%8,%9}, {%0,%1,%2,%3};"
                 : "+f"(c[0]), "+f"(c[1]), "+f"(c[2]), "+f"(c[3])
                 : "r"(a[0]), "r"(a[1]), "r"(a[2]), "r"(a[3]), "r"(b0), "r"(b1));
}

// ---------------------------------------------------------------------------
// small kernels
// ---------------------------------------------------------------------------
__global__ void means_k(const float* __restrict__ w, const float* __restrict__ b) {
    __shared__ float sw[32], sb[32];
    int t = threadIdx.x;
    float vw = w[t], vb = b[t];
    #pragma unroll
    for (int o = 16; o > 0; o >>= 1) {
        vw += __shfl_down_sync(0xffffffffu, vw, o);
        vb += __shfl_down_sync(0xffffffffu, vb, o);
    }
    if ((t & 31) == 0) { sw[t >> 5] = vw; sb[t >> 5] = vb; }
    __syncthreads();
    if (t < 32) {
        vw = sw[t]; vb = sb[t];
        #pragma unroll
        for (int o = 16; o > 0; o >>= 1) {
            vw += __shfl_down_sync(0xffffffffu, vw, o);
            vb += __shfl_down_sync(0xffffffffu, vb, o);
        }
        if (t == 0) { g_mw = vw / (float)Hc; g_mb = vb / (float)Hc; }
    }
}

__global__ void affine_k(const float4* __restrict__ x, f16* __restrict__ xh) {
    long i = (long)blockIdx.x * blockDim.x + threadIdx.x;
    float a = 1.0f + g_mw, c = g_mb;
    float4 v = x[i];
    ((__half2*)(xh + i * 4))[0] = __halves2half2(__float2half(v.x * a + c), __float2half(v.y * a + c));
    ((__half2*)(xh + i * 4))[1] = __halves2half2(__float2half(v.z * a + c), __float2half(v.w * a + c));
}

// W [K,N] fp32 -> WT fp16 [N,K]
__global__ void wsplit1(const float* __restrict__ W, f16* __restrict__ th, int K, int N) {
    __shared__ float t[32][33];
    int k0 = blockIdx.x * 32, n0 = blockIdx.y * 32;
    int tx = threadIdx.x, ty = threadIdx.y;
    #pragma unroll
    for (int i = ty; i < 32; i += 8)
        t[i][tx] = W[(long)(k0 + i) * N + n0 + tx];
    __syncthreads();
    #pragma unroll
    for (int i = ty; i < 32; i += 8)
        th[(long)(n0 + i) * K + k0 + tx] = __float2half(t[tx][i]);
}

// plain fp32 -> fp16 cast (no transpose), 4 elems/thread
__global__ void wcast(const float4* __restrict__ W, f16* __restrict__ o) {
    long i = (long)blockIdx.x * blockDim.x + threadIdx.x;
    float4 v = W[i];
    ((__half2*)(o + i * 4))[0] = __halves2half2(__float2half(v.x), __float2half(v.y));
    ((__half2*)(o + i * 4))[1] = __halves2half2(__float2half(v.z), __float2half(v.w));
}

__global__ void bcat(const float* __restrict__ bq, const float* __restrict__ bk,
                     const float* __restrict__ bv, float* __restrict__ o) {
    int i = blockIdx.x * 256 + threadIdx.x;
    o[i] = i < Hc ? bq[i] : (i < 2 * Hc ? bk[i - Hc] : bv[i - 2 * Hc]);
}

// bop[n] = bp[n] + sum_j bo[j] * wp[j,n]
__global__ void bop_k(const float* __restrict__ bo, const float* __restrict__ wp,
                      const float* __restrict__ bp, float* __restrict__ o) {
    int n = blockIdx.x * 256 + threadIdx.x;
    float s = bp[n];
    for (int j = 0; j < Hc; j++) s += bo[j] * wp[(long)j * Hc + n];
    o[n] = s;
}

// v slice of qkv (fp16, ld=3072, offset 2048) -> vT fp16 [(B*NH), HD, M]
__global__ void vsplitT(const f16* __restrict__ v, f16* __restrict__ th) {
    __shared__ float t[32][33];
    int z = blockIdx.z, zb = z >> 3, zh = z & 7;
    int m0 = blockIdx.x * 32, d0 = blockIdx.y * 32;
    int tx = threadIdx.x, ty = threadIdx.y;
    #pragma unroll
    for (int i = ty; i < 32; i += 8)
        t[i][tx] = __half2float(v[((long)zb * Mc + m0 + i) * 3072 + 2048 + zh * HDc + d0 + tx]);
    __syncthreads();
    #pragma unroll
    for (int i = ty; i < 32; i += 8)
        th[((long)z * HDc + d0 + i) * Mc + m0 + tx] = __float2half(t[tx][i]);
}

__global__ void ln_k(const float* __restrict__ in, const float* __restrict__ g,
                     const float* __restrict__ be, f16* __restrict__ oh) {
    long row = blockIdx.x;
    const float4* p = (const float4*)(in + row * Hc);
    int t = threadIdx.x;
    float4 v = p[t];
    float s  = v.x + v.y + v.z + v.w;
    float s2 = v.x * v.x + v.y * v.y + v.z * v.z + v.w * v.w;
    __shared__ float ss[8], ss2[8];
    #pragma unroll
    for (int of = 16; of > 0; of >>= 1) {
        s  += __shfl_down_sync(0xffffffffu, s, of);
        s2 += __shfl_down_sync(0xffffffffu, s2, of);
    }
    if ((t & 31) == 0) { ss[t >> 5] = s; ss2[t >> 5] = s2; }
    __syncthreads();
    __shared__ float mu_s, ri_s;
    if (t == 0) {
        float a = 0.f, b2 = 0.f;
        #pragma unroll
        for (int i = 0; i < 8; i++) { a += ss[i]; b2 += ss2[i]; }
        float mu = a / (float)Hc;
        mu_s = mu;
        ri_s = rsqrtf(b2 / (float)Hc - mu * mu + EPSc);
    }
    __syncthreads();
    float mu = mu_s, ri = ri_s;
    float4 gv = ((const float4*)g)[t];
    float4 bv = ((const float4*)be)[t];
    long o = row * Hc + t * 4;
    ((__half2*)(oh + o))[0] = __halves2half2(
        __float2half((v.x - mu) * ri * gv.x + bv.x), __float2half((v.y - mu) * ri * gv.y + bv.y));
    ((__half2*)(oh + o))[1] = __halves2half2(
        __float2half((v.z - mu) * ri * gv.z + bv.z), __float2half((v.w - mu) * ri * gv.w + bv.w));
}

// ---------------------------------------------------------------------------
// mma.sync fp16 GEMM: C[M,N] = alpha*(A @ B^T) (+bias)(relu)(+res)
//   OUT: 0 = fp32 C, 1 = fp16 Ch.  EPI bits: 1=bias, 2=relu, 4=residual
//   BM=128, BN=256, BK=64, 256 thr = 8 warps (2x4), warp tile 64x64, 3 stages.
// ---------------------------------------------------------------------------
#define NST 3
#define TILEB 16384                 // one 128x64 fp16 tile
#define ABYTES 16384                // A: 128x64
#define BBYTES 32768                // B: 256x64
#define STG_B (ABYTES + BBYTES)     // 49152 per stage

__device__ __forceinline__ void tile_cp(uint32_t sm, const f16* __restrict__ g, long ld, int tid) {
    int r = tid >> 3;
    int c16 = tid & 7;
    const char* gp = (const char*)(g + c16 * 8);
    #pragma unroll
    for (int i = 0; i < 4; i++) {
        int row = r + i * 32;
        uint32_t so = sm + row * 128 + ((c16 ^ (row & 7)) << 4);
        cp_async16(so, gp + (long)row * ld * 2);
    }
}

template<int OUT, int EPI>
__device__ __forceinline__ void store_pair(long off, long c, float v0, float v1,
                                           const float* __restrict__ bias,
                                           const float* __restrict__ Res,
                                           float* __restrict__ C, f16* __restrict__ Ch,
                                           float alpha) {
    v0 *= alpha; v1 *= alpha;
    if (EPI & 1) { v0 += bias[c]; v1 += bias[c + 1]; }
    if (EPI & 2) { v0 = fmaxf(v0, 0.f); v1 = fmaxf(v1, 0.f); }
    if (EPI & 4) {
        float2 rv = *(const float2*)(Res + off);
        v0 += rv.x; v1 += rv.y;
    }
    if (OUT == 0) {
        *(float2*)(C + off) = make_float2(v0, v1);
    } else {
        *(__half2*)(Ch + off) = __halves2half2(__float2half(v0), __float2half(v1));
    }
}

template<int OUT, int EPI>
__global__ void __launch_bounds__(256, 1)
mmk(const f16* __restrict__ Ah, const f16* __restrict__ Bh,
    const float* __restrict__ bias, const float* __restrict__ Res,
    float* __restrict__ C, f16* __restrict__ Ch,
    int Kdim, int lda, int ldb, int ldc,
    int nh, long sA0, long sA1, long sB0, long sB1, long sC0, long sC1,
    float alpha)
{
    extern __shared__ __align__(1024) char smem[];
    const uint32_t sb = smem_u32(smem);
    const int tid = threadIdx.x;
    const int wid = tid >> 5, l = tid & 31;
    const int wm = wid >> 2, wn = wid & 3;

    const int z = blockIdx.z;
    const long zb = z / nh, zh = z - zb * (long)nh;
    const long row0 = (long)blockIdx.y * 128;
    const long col0 = (long)blockIdx.x * 256;

    const f16* pAh = Ah + zb * sA0 + zh * sA1 + row0 * lda;
    const f16* pBh = Bh + zb * sB0 + zh * sB1 + col0 * ldb;

    float acc[4][8][4];
    #pragma unroll
    for (int i = 0; i < 4; i++)
        #pragma unroll
        for (int j = 0; j < 8; j++)
            #pragma unroll
            for (int r = 0; r < 4; r++) acc[i][j][r] = 0.0f;

    const int nchunk = Kdim >> 6;

    #pragma unroll
    for (int s = 0; s < NST - 1; s++) {
        if (s < nchunk) {
            uint32_t st = sb + s * STG_B;
            long k0 = (long)s << 6;
            tile_cp(st,                  pAh + k0, lda, tid);
            tile_cp(st + ABYTES,         pBh + k0, ldb, tid);
            tile_cp(st + ABYTES + TILEB, pBh + 128 * ldb + k0, ldb, tid);
        }
        cp_commit();
    }

    const int ar = l & 15, asel = l >> 4, swa = l & 7;
    const int br = ((l >> 4) << 3) + (l & 7), bsel = (l >> 3) & 1;
    const int swb = br & 7;

    for (int c = 0; c < nchunk; c++) {
        cp_wait<1>();
        __syncthreads();
        if (c + 2 < nchunk) {
            uint32_t st = sb + ((c + 2) % NST) * STG_B;
            long k0 = (long)(c + 2) << 6;
            tile_cp(st,                  pAh + k0, lda, tid);
            tile_cp(st + ABYTES,         pBh + k0, ldb, tid);
            tile_cp(st + ABYTES + TILEB, pBh + 128 * ldb + k0, ldb, tid);
        }
        cp_commit();

        const uint32_t st = sb + (c % NST) * STG_B;
        #pragma unroll
        for (int kp = 0; kp < 4; kp++) {
            uint32_t aH[4][4], bH[8][2];
            #pragma unroll
            for (int mt = 0; mt < 4; mt++) {
                int row = wm * 64 + mt * 16 + ar;
                uint32_t ad = st + row * 128 + (((kp * 2 + asel) ^ swa) << 4);
                ldsm4(aH[mt][0], aH[mt][1], aH[mt][2], aH[mt][3], ad);
            }
            #pragma unroll
            for (int np = 0; np < 4; np++) {
                int row = wn * 64 + np * 16 + br;
                uint32_t bd = st + ABYTES + row * 128 + (((kp * 2 + bsel) ^ swb) << 4);
                ldsm4(bH[np*2][0], bH[np*2][1], bH[np*2+1][0], bH[np*2+1][1], bd);
            }
            #pragma unroll
            for (int mt = 0; mt < 4; mt++)
                #pragma unroll
                for (int nt = 0; nt < 8; nt++)
                    mma16816(acc[mt][nt], aH[mt], bH[nt][0], bH[nt][1]);
        }
        __syncthreads();
    }

    const long Rw = row0 + wm * 64;
    const long Cw = col0 + wn * 64;
    const long base = zb * sC0 + zh * sC1;
    const int lr = l >> 2, lc = (l & 3) * 2;
    #pragma unroll
    for (int mt = 0; mt < 4; mt++) {
        long r0 = Rw + mt * 16 + lr;
        #pragma unroll
        for (int nt = 0; nt < 8; nt++) {
            long cc = Cw + nt * 8 + lc;
            store_pair<OUT, EPI>(base + r0 * ldc + cc, cc, acc[mt][nt][0], acc[mt][nt][1],
                                 bias, Res, C, Ch, alpha);
            store_pair<OUT, EPI>(base + (r0 + 8) * ldc + cc, cc, acc[mt][nt][2], acc[mt][nt][3],
                                 bias, Res, C, Ch, alpha);
        }
    }
}

// ---------------------------------------------------------------------------
// Fused attention (unchanged from R9): per CTA = one 128-row q-tile of one (b,h).
// smem: Q[2] | buf0: K[2] V[2] | buf1: K[2] V[2]  = 10 * TILEB = 160 KB
// ---------------------------------------------------------------------------
__global__ void __launch_bounds__(256, 1)
fattn(const f16* __restrict__ qkv, const f16* __restrict__ vt, f16* __restrict__ outp)
{
    extern __shared__ __align__(1024) char smem[];
    const uint32_t sb = smem_u32(smem);
    const int tid = threadIdx.x;
    const int w = tid >> 5, l = tid & 31;
    const int by = blockIdx.x;                 // q-tile 0..3
    const int z  = blockIdx.y;                 // b*8 + h
    const int b = z >> 3, h = z & 7;

    const long qrow0 = (long)b * Mc + by * 128;
    const f16* pQ  = qkv + qrow0 * 3072 + h * HDc;
    const f16* pK0 = qkv + (long)b * Mc * 3072 + Hc + h * HDc;
    const f16* pV0 = vt + (long)z * HDc * Mc;

    tile_cp(sb + 0 * TILEB, pQ,      3072, tid);
    tile_cp(sb + 1 * TILEB, pQ + 64, 3072, tid);
    tile_cp(sb + 2 * TILEB, pK0,      3072, tid);
    tile_cp(sb + 3 * TILEB, pK0 + 64, 3072, tid);
    tile_cp(sb + 4 * TILEB, pV0,      Mc, tid);
    tile_cp(sb + 5 * TILEB, pV0 + 64, Mc, tid);
    cp_commit();

    float oacc[16][4];
    #pragma unroll
    for (int i = 0; i < 16; i++)
        #pragma unroll
        for (int c = 0; c < 4; c++) oacc[i][c] = 0.0f;
    float mprev[2] = {-1e30f, -1e30f};
    float lsum[2]  = {0.0f, 0.0f};

    const int ar = l & 15, asel = l >> 4;
    const int br = ((l >> 4) << 3) + (l & 7), bsel = (l >> 3) & 1;
    const int sw = l & 7;
    const float alpha = 0.08838834764831845f;   // 1/sqrt(128)

    for (int j = 0; j < 4; j++) {
        const int buf = j & 1;
        if (j < 3) {
            const int nb_ = buf ^ 1;
            const f16* pK = pK0 + (long)(j + 1) * 128 * 3072;
            const f16* pV = pV0 + (j + 1) * 128;
            tile_cp(sb + (2 + nb_ * 4 + 0) * TILEB, pK,      3072, tid);
            tile_cp(sb + (2 + nb_ * 4 + 1) * TILEB, pK + 64, 3072, tid);
            tile_cp(sb + (2 + nb_ * 4 + 2) * TILEB, pV,      Mc, tid);
            tile_cp(sb + (2 + nb_ * 4 + 3) * TILEB, pV + 64, Mc, tid);
            cp_commit();
            cp_wait<1>();
        } else {
            cp_wait<0>();
        }
        __syncthreads();

        const uint32_t sK = sb + (2 + buf * 4) * TILEB;
        const uint32_t sV = sK + 2 * TILEB;

        float sacc[16][4];
        #pragma unroll
        for (int i = 0; i < 16; i++)
            #pragma unroll
            for (int c = 0; c < 4; c++) sacc[i][c] = 0.0f;

        #pragma unroll
        for (int kp = 0; kp < 8; kp++) {
            uint32_t aq[4];
            uint32_t qa = sb + (kp >> 2) * TILEB + (w * 16 + ar) * 128
                        + ((((kp & 3) * 2 + asel) ^ sw) << 4);
            ldsm4(aq[0], aq[1], aq[2], aq[3], qa);
            #pragma unroll
            for (int nb = 0; nb < 8; nb++) {
                uint32_t b0, b1, b2, b3;
                uint32_t ka = sK + (kp >> 2) * TILEB + (nb * 16 + br) * 128
                            + ((((kp & 3) * 2 + bsel) ^ sw) << 4);
                ldsm4(b0, b1, b2, b3, ka);
                mma16816(sacc[nb * 2],     aq, b0, b1);
                mma16816(sacc[nb * 2 + 1], aq, b2, b3);
            }
        }

        #pragma unroll
        for (int i = 0; i < 16; i++)
            #pragma unroll
            for (int c = 0; c < 4; c++) sacc[i][c] *= alpha;
        if (by == j) {
            int r0 = w * 16 + (l >> 2);
            #pragma unroll
            for (int nt = 0; nt < 16; nt++) {
                int cb = nt * 8 + (l & 3) * 2;
                if (cb     == r0)     sacc[nt][0] = 0.0f;
                if (cb + 1 == r0)     sacc[nt][1] = 0.0f;
                if (cb     == r0 + 8) sacc[nt][2] = 0.0f;
                if (cb + 1 == r0 + 8) sacc[nt][3] = 0.0f;
            }
        }

        #pragma unroll
        for (int g = 0; g < 2; g++) {
            float mx = -1e30f;
            #pragma unroll
            for (int nt = 0; nt < 16; nt++)
                mx = fmaxf(mx, fmaxf(sacc[nt][2 * g], sacc[nt][2 * g + 1]));
            mx = fmaxf(mx, __shfl_xor_sync(0xffffffffu, mx, 1));
            mx = fmaxf(mx, __shfl_xor_sync(0xffffffffu, mx, 2));
            float mnew = fmaxf(mprev[g], mx);
            float sc = __expf(mprev[g] - mnew);
            float sum = 0.0f;
            #pragma unroll
            for (int nt = 0; nt < 16; nt++) {
                float e0 = __expf(sacc[nt][2 * g]     - mnew);
                float e1 = __expf(sacc[nt][2 * g + 1] - mnew);
                sacc[nt][2 * g] = e0; sacc[nt][2 * g + 1] = e1;
                sum += e0 + e1;
            }
            sum += __shfl_xor_sync(0xffffffffu, sum, 1);
            sum += __shfl_xor_sync(0xffffffffu, sum, 2);
            lsum[g] = lsum[g] * sc + sum;
            mprev[g] = mnew;
            #pragma unroll
            for (int nt = 0; nt < 16; nt++) {
                oacc[nt][2 * g]     *= sc;
                oacc[nt][2 * g + 1] *= sc;
            }
        }

        uint32_t aP[8][4];
        #pragma unroll
        for (int t = 0; t < 8; t++) {
            aP[t][0] = f2h2(sacc[2*t][0],   sacc[2*t][1]);
            aP[t][1] = f2h2(sacc[2*t][2],   sacc[2*t][3]);
            aP[t][2] = f2h2(sacc[2*t+1][0], sacc[2*t+1][1]);
            aP[t][3] = f2h2(sacc[2*t+1][2], sacc[2*t+1][3]);
        }

        #pragma unroll
        for (int t = 0; t < 8; t++) {
            #pragma unroll
            for (int nb = 0; nb < 8; nb++) {
                uint32_t b0, b1, b2, b3;
                uint32_t va = sV + (t >> 2) * TILEB + (nb * 16 + br) * 128
                            + ((((t & 3) * 2 + bsel) ^ sw) << 4);
                ldsm4(b0, b1, b2, b3, va);
                mma16816(oacc[nb * 2],     aP[t], b0, b1);
                mma16816(oacc[nb * 2 + 1], aP[t], b2, b3);
            }
        }
        __syncthreads();
    }

    #pragma unroll
    for (int g = 0; g < 2; g++) {
        float inv = 1.0f / lsum[g];
        long m = qrow0 + w * 16 + (l >> 2) + 8 * g;
        f16* op = outp + m * Hc + h * HDc + (l & 3) * 2;
        #pragma unroll
        for (int nt = 0; nt < 16; nt++) {
            float v0 = oacc[nt][2 * g] * inv, v1 = oacc[nt][2 * g + 1] * inv;
            *(__half2*)(op + nt * 8) = __halves2half2(__float2half(v0), __float2half(v1));
        }
    }
}

// ---------------------------------------------------------------------------
// Launch
// ---------------------------------------------------------------------------
extern "C" void kernel_launch(void* const* d_in, const int* in_sizes, int n_in,
                              void* d_out, int out_size)
{
    const float* x      = (const float*)d_in[0];
    const float* conv_w = (const float*)d_in[1];
    const float* conv_b = (const float*)d_in[2];
    const float* w1 = (const float*)d_in[3];
    const float* b1 = (const float*)d_in[4];
    const float* w2 = (const float*)d_in[5];
    const float* b2 = (const float*)d_in[6];
    const float* ln_g = (const float*)d_in[7];
    const float* ln_b = (const float*)d_in[8];
    const float* wq = (const float*)d_in[9];
    const float* bq = (const float*)d_in[10];
    const float* wk = (const float*)d_in[11];
    const float* bk = (const float*)d_in[12];
    const float* wv = (const float*)d_in[13];
    const float* bv = (const float*)d_in[14];
    const float* wo = (const float*)d_in[15];
    const float* bo = (const float*)d_in[16];
    const float* wp = (const float*)d_in[17];
    const float* bp = (const float*)d_in[18];
    float* out = (float*)d_out;

    #define SYM(p, s) void* p; cudaGetSymbolAddress(&p, s)
    SYM(xah, g_xah);
    SYM(h1, g_h1);
    SYM(xreg, g_xreg);
    SYM(xnh, g_xnh);
    SYM(qkv, g_qkv); SYM(vth, g_vth);
    SYM(ch, g_ch);
    SYM(w1t, g_w1t); SYM(w2t, g_w2t);
    SYM(wqkv, g_wqkv); SYM(bqkv, g_bqkv);
    SYM(wo16, g_wo16); SYM(wpt, g_wpt); SYM(wopT, g_wopT); SYM(bop, g_bop);
    #undef SYM

    const int SMB_1 = NST * STG_B;       // 147456
    const int SMB_F = 10 * TILEB;        // 163840
    cudaFuncSetAttribute(mmk<1,3>, cudaFuncAttributeMaxDynamicSharedMemorySize, SMB_1);
    cudaFuncSetAttribute(mmk<0,1>, cudaFuncAttributeMaxDynamicSharedMemorySize, SMB_1);
    cudaFuncSetAttribute(mmk<1,1>, cudaFuncAttributeMaxDynamicSharedMemorySize, SMB_1);
    cudaFuncSetAttribute(mmk<1,0>, cudaFuncAttributeMaxDynamicSharedMemorySize, SMB_1);
    cudaFuncSetAttribute(mmk<0,5>, cudaFuncAttributeMaxDynamicSharedMemorySize, SMB_1);
    cudaFuncSetAttribute(fattn, cudaFuncAttributeMaxDynamicSharedMemorySize, SMB_F);

    const int BMrows = Bc * Mc;  // 32768

    // 1. conv means, affine -> fp16
    means_k<<<1, 1024>>>(conv_w, conv_b);
    affine_k<<<(unsigned)(BMM / 4 / 256), 256>>>((const float4*)x, (f16*)xah);

    // 2. weight prep
    wsplit1<<<dim3(Mc/32, Hc/32), dim3(32,8)>>>(w1, (f16*)w1t, Mc, Hc);
    wsplit1<<<dim3(Hc/32, Hc/32), dim3(32,8)>>>(w2, (f16*)w2t, Hc, Hc);
    wsplit1<<<dim3(Hc/32, Hc/32), dim3(32,8)>>>(wq, (f16*)wqkv,                   Hc, Hc);
    wsplit1<<<dim3(Hc/32, Hc/32), dim3(32,8)>>>(wk, (f16*)wqkv + (size_t)Hc*Hc,   Hc, Hc);
    wsplit1<<<dim3(Hc/32, Hc/32), dim3(32,8)>>>(wv, (f16*)wqkv + (size_t)2*Hc*Hc, Hc, Hc);
    wcast<<<Hc*Hc/4/256, 256>>>((const float4*)wo, (f16*)wo16);
    wsplit1<<<dim3(Hc/32, Hc/32), dim3(32,8)>>>(wp, (f16*)wpt, Hc, Hc);
    bcat<<<12, 256>>>(bq, bk, bv, (float*)bqkv);
    bop_k<<<4, 256>>>(bo, wp, bp, (float*)bop);

    // 3. wopT[n,j] = sum_k wp[k,n]·wo[j,k] = (wo@wp)^T  -> [N,K] for final GEMM
    mmk<1,0><<<dim3(Hc/256, Hc/128, 1), 256, SMB_1>>>(
        (f16*)wpt, (f16*)wo16, nullptr, nullptr, nullptr, (f16*)wopT,
        Hc, Hc, Hc, Hc, 1, 0,0,0,0,0,0, 1.0f);

    // 4. h1 = relu(xa @ w1 + b1) -> fp16
    mmk<1,3><<<dim3(Hc/256, BMrows/128, 1), 256, SMB_1>>>(
        (f16*)xah, (f16*)w1t, b1, nullptr, nullptr, (f16*)h1,
        Mc, Mc, Mc, Hc, 1, 0,0,0,0,0,0, 1.0f);

    // 5. xreg = h1 @ w2 + b2 (fp32)
    mmk<0,1><<<dim3(Hc/256, BMrows/128, 1), 256, SMB_1>>>(
        (f16*)h1, (f16*)w2t, b2, nullptr, (float*)xreg, nullptr,
        Hc, Hc, Hc, Hc, 1, 0,0,0,0,0,0, 1.0f);

    // 6. layernorm -> fp16
    ln_k<<<BMrows, 256>>>((const float*)xreg, ln_g, ln_b, (f16*)xnh);

    // 7. fused q|k|v projection
    mmk<1,1><<<dim3(3*Hc/256, BMrows/128, 1), 256, SMB_1>>>(
        (f16*)xnh, (f16*)wqkv, (const float*)bqkv, nullptr, nullptr, (f16*)qkv,
        Hc, Hc, Hc, 3*Hc, 1, 0,0,0,0,0,0, 1.0f);

    // 8. vT fp16 [B*NH, HD, M]
    vsplitT<<<dim3(Mc/32, HDc/32, Bc*NHc), dim3(32,8)>>>((const f16*)qkv, (f16*)vth);

    // 9. fused attention -> ch
    fattn<<<dim3(Mc/128, Bc*NHc), 256, SMB_F>>>((const f16*)qkv, (const f16*)vth, (f16*)ch);

    // 10. out = ctx @ (wo@wp) + (bo@wp + bp) + xreg (fp32)
    mmk<0,5><<<dim3(Hc/256, BMrows/128, 1), 256, SMB_1>>>(
        (f16*)ch, (f16*)wopT, (const float*)bop, (const float*)xreg, out, nullptr,
        Hc, Hc, Hc, Hc, 1, 0,0,0,0,0,0, 1.0f);
}

// round 15
// speedup vs baseline: 1.0126x; 1.0126x over previous
#include <cuda_runtime.h>
#include <cuda_fp16.h>
#include <cstdint>

#define Bc  64
#define Mc  512
#define Hc  1024
#define NHc 8
#define HDc 128
#define EPSc 1e-5f

typedef __half f16;

#define BMH ((size_t)Bc*Mc*Hc)
#define BMM ((size_t)Bc*Mc*Mc)

// ---------------------------------------------------------------------------
// Scratch (static device globals — allocation-free)
// ---------------------------------------------------------------------------
__device__ float g_mw, g_mb;
__device__ f16 g_xah[BMM];
__device__ f16 g_h1[BMH];
__device__ float g_xreg[BMH];
__device__ f16 g_xnh[BMH];
__device__ f16 g_qkv[(size_t)Bc*Mc*3*Hc];         // [B*M, 3072] = q|k|v
__device__ f16 g_vth[BMH];                        // [B*NH, 128, 512]
__device__ f16 g_ch[BMH];
// fp16 weights
__device__ f16 g_w1t[(size_t)Hc*Mc];              // [N,K]
__device__ f16 g_w2t[(size_t)Hc*Hc];              // [N,K]
__device__ f16 g_wqkv[(size_t)3*Hc*Hc];           // [3072, 1024]
__device__ f16 g_wo16[(size_t)Hc*Hc];             // wo row-major (untransposed!)
__device__ f16 g_wpt[(size_t)Hc*Hc];              // [N,K]
__device__ f16 g_wopT[(size_t)Hc*Hc];             // (wo@wp)^T in [N,K]
__device__ float g_bqkv[3*Hc];
__device__ float g_bop[Hc];                       // bo@wp + bp

// ---------------------------------------------------------------------------
// PTX helpers (baseline PTX only — no tcgen05 on compute_103)
// ---------------------------------------------------------------------------
__device__ __forceinline__ uint32_t smem_u32(const void* p) {
    uint32_t a;
    asm("{ .reg .u64 t; cvta.to.shared.u64 t, %1; cvt.u32.u64 %0, t; }"
        : "=r"(a) : "l"(p));
    return a;
}

// pack two fp32 -> u32 {hi:f16(hi), lo:f16(lo)}
__device__ __forceinline__ uint32_t f2h2(float lo, float hi) {
    uint32_t r;
    asm("cvt.rn.f16x2.f32 %0, %1, %2;" : "=r"(r) : "f"(hi), "f"(lo));
    return r;
}

__device__ __forceinline__ void cp_async16(uint32_t saddr, const void* gaddr) {
    asm volatile("cp.async.cg.shared.global [%0], [%1], 16;\n"
                 :: "r"(saddr), "l"(gaddr));
}
__device__ __forceinline__ void cp_commit() {
    asm volatile("cp.async.commit_group;\n" ::: "memory");
}
template<int N>
__device__ __forceinline__ void cp_wait() {
    asm volatile("cp.async.wait_group %0;\n" :: "n"(N) : "memory");
}

__device__ __forceinline__ void ldsm4(uint32_t& r0, uint32_t& r1, uint32_t& r2, uint32_t& r3,
                                      uint32_t addr) {
    asm volatile("ldmatrix.sync.aligned.m8n8.x4.shared.b16 {%0,%1,%2,%3}, [%4];"
                 : "=r"(r0), "=r"(r1), "=r"(r2), "=r"(r3) : "r"(addr));
}

__device__ __forceinline__ void mma16816(float* c, const uint32_t* a, uint32_t b0, uint32_t b1) {
    asm volatile("mma.sync.aligned.m16n8k16.row.col.f32.f16.f16.f32 "
                 "{%0,%1,%2,%3}, {%4,%5,%6,%7}, {%8,%9}, {%0,%1,%2,%3};"
                 : "+f"(c[0]), "+f"(c[1]), "+f"(c[2]), "+f"(c[3])
                 : "r"(a[0]), "r"(a[1]), "r"(a[2]), "r"(a[3]), "r"(b0), "r"(b1));
}

// ---------------------------------------------------------------------------
// small kernels
// ---------------------------------------------------------------------------
__global__ void means_k(const float* __restrict__ w, const float* __restrict__ b) {
    __shared__ float sw[32], sb[32];
    int t = threadIdx.x;
    float vw = w[t], vb = b[t];
    #pragma unroll
    for (int o = 16; o > 0; o >>= 1) {
        vw += __shfl_down_sync(0xffffffffu, vw, o);
        vb += __shfl_down_sync(0xffffffffu, vb, o);
    }
    if ((t & 31) == 0) { sw[t >> 5] = vw; sb[t >> 5] = vb; }
    __syncthreads();
    if (t < 32) {
        vw = sw[t]; vb = sb[t];
        #pragma unroll
        for (int o = 16; o > 0; o >>= 1) {
            vw += __shfl_down_sync(0xffffffffu, vw, o);
            vb += __shfl_down_sync(0xffffffffu, vb, o);
        }
        if (t == 0) { g_mw = vw / (float)Hc; g_mb = vb / (float)Hc; }
    }
}

__global__ void affine_k(const float4* __restrict__ x, f16* __restrict__ xh) {
    long i = (long)blockIdx.x * blockDim.x + threadIdx.x;
    float a = 1.0f + g_mw, c = g_mb;
    float4 v = x[i];
    ((__half2*)(xh + i * 4))[0] = __halves2half2(__float2half(v.x * a + c), __float2half(v.y * a + c));
    ((__half2*)(xh + i * 4))[1] = __halves2half2(__float2half(v.z * a + c), __float2half(v.w * a + c));
}

// W [K,N] fp32 -> WT fp16 [N,K]
__global__ void wsplit1(const float* __restrict__ W, f16* __restrict__ th, int K, int N) {
    __shared__ float t[32][33];
    int k0 = blockIdx.x * 32, n0 = blockIdx.y * 32;
    int tx = threadIdx.x, ty = threadIdx.y;
    #pragma unroll
    for (int i = ty; i < 32; i += 8)
        t[i][tx] = W[(long)(k0 + i) * N + n0 + tx];
    __syncthreads();
    #pragma unroll
    for (int i = ty; i < 32; i += 8)
        th[(long)(n0 + i) * K + k0 + tx] = __float2half(t[tx][i]);
}

// plain fp32 -> fp16 cast (no transpose), 4 elems/thread
__global__ void wcast(const float4* __restrict__ W, f16* __restrict__ o) {
    long i = (long)blockIdx.x * blockDim.x + threadIdx.x;
    float4 v = W[i];
    ((__half2*)(o + i * 4))[0] = __halves2half2(__float2half(v.x), __float2half(v.y));
    ((__half2*)(o + i * 4))[1] = __halves2half2(__float2half(v.z), __float2half(v.w));
}

__global__ void bcat(const float* __restrict__ bq, const float* __restrict__ bk,
                     const float* __restrict__ bv, float* __restrict__ o) {
    int i = blockIdx.x * 256 + threadIdx.x;
    o[i] = i < Hc ? bq[i] : (i < 2 * Hc ? bk[i - Hc] : bv[i - 2 * Hc]);
}

// bop[n] = bp[n] + sum_j bo[j] * wp[j,n]
__global__ void bop_k(const float* __restrict__ bo, const float* __restrict__ wp,
                      const float* __restrict__ bp, float* __restrict__ o) {
    int n = blockIdx.x * 256 + threadIdx.x;
    float s = bp[n];
    for (int j = 0; j < Hc; j++) s += bo[j] * wp[(long)j * Hc + n];
    o[n] = s;
}

// v slice of qkv (fp16, ld=3072, offset 2048) -> vT fp16 [(B*NH), HD, M]
__global__ void vsplitT(const f16* __restrict__ v, f16* __restrict__ th) {
    __shared__ float t[32][33];
    int z = blockIdx.z, zb = z >> 3, zh = z & 7;
    int m0 = blockIdx.x * 32, d0 = blockIdx.y * 32;
    int tx = threadIdx.x, ty = threadIdx.y;
    #pragma unroll
    for (int i = ty; i < 32; i += 8)
        t[i][tx] = __half2float(v[((long)zb * Mc + m0 + i) * 3072 + 2048 + zh * HDc + d0 + tx]);
    __syncthreads();
    #pragma unroll
    for (int i = ty; i < 32; i += 8)
        th[((long)z * HDc + d0 + i) * Mc + m0 + tx] = __float2half(t[tx][i]);
}

__global__ void ln_k(const float* __restrict__ in, const float* __restrict__ g,
                     const float* __restrict__ be, f16* __restrict__ oh) {
    long row = blockIdx.x;
    const float4* p = (const float4*)(in + row * Hc);
    int t = threadIdx.x;
    float4 v = p[t];
    float s  = v.x + v.y + v.z + v.w;
    float s2 = v.x * v.x + v.y * v.y + v.z * v.z + v.w * v.w;
    __shared__ float ss[8], ss2[8];
    #pragma unroll
    for (int of = 16; of > 0; of >>= 1) {
        s  += __shfl_down_sync(0xffffffffu, s, of);
        s2 += __shfl_down_sync(0xffffffffu, s2, of);
    }
    if ((t & 31) == 0) { ss[t >> 5] = s; ss2[t >> 5] = s2; }
    __syncthreads();
    __shared__ float mu_s, ri_s;
    if (t == 0) {
        float a = 0.f, b2 = 0.f;
        #pragma unroll
        for (int i = 0; i < 8; i++) { a += ss[i]; b2 += ss2[i]; }
        float mu = a / (float)Hc;
        mu_s = mu;
        ri_s = rsqrtf(b2 / (float)Hc - mu * mu + EPSc);
    }
    __syncthreads();
    float mu = mu_s, ri = ri_s;
    float4 gv = ((const float4*)g)[t];
    float4 bv = ((const float4*)be)[t];
    long o = row * Hc + t * 4;
    ((__half2*)(oh + o))[0] = __halves2half2(
        __float2half((v.x - mu) * ri * gv.x + bv.x), __float2half((v.y - mu) * ri * gv.y + bv.y));
    ((__half2*)(oh + o))[1] = __halves2half2(
        __float2half((v.z - mu) * ri * gv.z + bv.z), __float2half((v.w - mu) * ri * gv.w + bv.w));
}

// ---------------------------------------------------------------------------
// mma.sync fp16 GEMM (R9 config): C[M,N] = alpha*(A @ B^T) (+bias)(relu)(+res)
//   OUT: 0 = fp32 C, 1 = fp16 Ch.  EPI bits: 1=bias, 2=relu, 4=residual
//   BM=BN=128, BK=64, 256 thr = 8 warps (2x4), warp tile 64x32, 3 stages.
// ---------------------------------------------------------------------------
#define NST 3
#define TILEB 16384                 // one 128x64 fp16 tile

__device__ __forceinline__ void tile_cp(uint32_t sm, const f16* __restrict__ g, long ld, int tid) {
    int r = tid >> 3;
    int c16 = tid & 7;
    const char* gp = (const char*)(g + c16 * 8);
    #pragma unroll
    for (int i = 0; i < 4; i++) {
        int row = r + i * 32;
        uint32_t so = sm + row * 128 + ((c16 ^ (row & 7)) << 4);
        cp_async16(so, gp + (long)row * ld * 2);
    }
}

template<int OUT, int EPI>
__device__ __forceinline__ void store_pair(long off, long c, float v0, float v1,
                                           const float* __restrict__ bias,
                                           const float* __restrict__ Res,
                                           float* __restrict__ C, f16* __restrict__ Ch,
                                           float alpha) {
    v0 *= alpha; v1 *= alpha;
    if (EPI & 1) { v0 += bias[c]; v1 += bias[c + 1]; }
    if (EPI & 2) { v0 = fmaxf(v0, 0.f); v1 = fmaxf(v1, 0.f); }
    if (EPI & 4) {
        float2 rv = *(const float2*)(Res + off);
        v0 += rv.x; v1 += rv.y;
    }
    if (OUT == 0) {
        *(float2*)(C + off) = make_float2(v0, v1);
    } else {
        *(__half2*)(Ch + off) = __halves2half2(__float2half(v0), __float2half(v1));
    }
}

template<int OUT, int EPI>
__global__ void __launch_bounds__(256, 2)
mmk(const f16* __restrict__ Ah, const f16* __restrict__ Bh,
    const float* __restrict__ bias, const float* __restrict__ Res,
    float* __restrict__ C, f16* __restrict__ Ch,
    int Kdim, int lda, int ldb, int ldc,
    int nh, long sA0, long sA1, long sB0, long sB1, long sC0, long sC1,
    float alpha)
{
    extern __shared__ __align__(1024) char smem[];
    constexpr int STAGEB = 2 * TILEB;

    const uint32_t sb = smem_u32(smem);
    const int tid = threadIdx.x;
    const int wid = tid >> 5, l = tid & 31;
    const int wm = wid >> 2, wn = wid & 3;

    const int z = blockIdx.z;
    const long zb = z / nh, zh = z - zb * (long)nh;
    const long row0 = (long)blockIdx.y * 128;
    const long col0 = (long)blockIdx.x * 128;

    const f16* pAh = Ah + zb * sA0 + zh * sA1 + row0 * lda;
    const f16* pBh = Bh + zb * sB0 + zh * sB1 + col0 * ldb;

    float acc[4][4][4];
    #pragma unroll
    for (int i = 0; i < 4; i++)
        #pragma unroll
        for (int j = 0; j < 4; j++)
            #pragma unroll
            for (int r = 0; r < 4; r++) acc[i][j][r] = 0.0f;

    const int nchunk = Kdim >> 6;

    #pragma unroll
    for (int s = 0; s < NST - 1; s++) {
        if (s < nchunk) {
            uint32_t st = sb + s * STAGEB;
            long k0 = (long)s << 6;
            tile_cp(st,         pAh + k0, lda, tid);
            tile_cp(st + TILEB, pBh + k0, ldb, tid);
        }
        cp_commit();
    }

    const int ar = l & 15, asel = l >> 4, swa = l & 7;
    const int br = ((l >> 4) << 3) + (l & 7), bsel = (l >> 3) & 1;
    const int swb = br & 7;

    for (int c = 0; c < nchunk; c++) {
        cp_wait<1>();
        __syncthreads();
        if (c + 2 < nchunk) {
            uint32_t st = sb + ((c + 2) % NST) * STAGEB;
            long k0 = (long)(c + 2) << 6;
            tile_cp(st,         pAh + k0, lda, tid);
            tile_cp(st + TILEB, pBh + k0, ldb, tid);
        }
        cp_commit();

        const uint32_t st = sb + (c % NST) * STAGEB;
        #pragma unroll
        for (int kp = 0; kp < 4; kp++) {
            uint32_t aH[4][4], bH[4][2];
            #pragma unroll
            for (int mt = 0; mt < 4; mt++) {
                int row = wm * 64 + mt * 16 + ar;
                uint32_t ad = st + row * 128 + (((kp * 2 + asel) ^ swa) << 4);
                ldsm4(aH[mt][0], aH[mt][1], aH[mt][2], aH[mt][3], ad);
            }
            #pragma unroll
            for (int np = 0; np < 2; np++) {
                int row = wn * 32 + np * 16 + br;
                uint32_t bd = st + TILEB + row * 128 + (((kp * 2 + bsel) ^ swb) << 4);
                ldsm4(bH[np*2][0], bH[np*2][1], bH[np*2+1][0], bH[np*2+1][1], bd);
            }
            #pragma unroll
            for (int mt = 0; mt < 4; mt++)
                #pragma unroll
                for (int nt = 0; nt < 4; nt++)
                    mma16816(acc[mt][nt], aH[mt], bH[nt][0], bH[nt][1]);
        }
        __syncthreads();
    }

    const long Rw = row0 + wm * 64;
    const long Cw = col0 + wn * 32;
    const long base = zb * sC0 + zh * sC1;
    const int lr = l >> 2, lc = (l & 3) * 2;
    #pragma unroll
    for (int mt = 0; mt < 4; mt++) {
        long r0 = Rw + mt * 16 + lr;
        #pragma unroll
        for (int nt = 0; nt < 4; nt++) {
            long cc = Cw + nt * 8 + lc;
            store_pair<OUT, EPI>(base + r0 * ldc + cc, cc, acc[mt][nt][0], acc[mt][nt][1],
                                 bias, Res, C, Ch, alpha);
            store_pair<OUT, EPI>(base + (r0 + 8) * ldc + cc, cc, acc[mt][nt][2], acc[mt][nt][3],
                                 bias, Res, C, Ch, alpha);
        }
    }
}

// ---------------------------------------------------------------------------
// Fused attention v2: single-buffered K/V, 2 CTAs/SM (inter-CTA overlap).
//   per CTA = one 128-row q-tile of one (b,h); 8 warps, 16 q-rows each.
// smem: Q[2] | K[2] | V[2] = 6 * TILEB = 96 KB
// ---------------------------------------------------------------------------
__global__ void __launch_bounds__(256, 2)
fattn(const f16* __restrict__ qkv, const f16* __restrict__ vt, f16* __restrict__ outp)
{
    extern __shared__ __align__(1024) char smem[];
    const uint32_t sb = smem_u32(smem);
    const int tid = threadIdx.x;
    const int w = tid >> 5, l = tid & 31;
    const int by = blockIdx.x;                 // q-tile 0..3
    const int z  = blockIdx.y;                 // b*8 + h
    const int b = z >> 3, h = z & 7;

    const long qrow0 = (long)b * Mc + by * 128;
    const f16* pQ  = qkv + qrow0 * 3072 + h * HDc;
    const f16* pK0 = qkv + (long)b * Mc * 3072 + Hc + h * HDc;
    const f16* pV0 = vt + (long)z * HDc * Mc;

    // prologue: Q + K0/V0 (single buffer)
    tile_cp(sb + 0 * TILEB, pQ,      3072, tid);
    tile_cp(sb + 1 * TILEB, pQ + 64, 3072, tid);
    tile_cp(sb + 2 * TILEB, pK0,      3072, tid);
    tile_cp(sb + 3 * TILEB, pK0 + 64, 3072, tid);
    tile_cp(sb + 4 * TILEB, pV0,      Mc, tid);
    tile_cp(sb + 5 * TILEB, pV0 + 64, Mc, tid);
    cp_commit();

    float oacc[16][4];
    #pragma unroll
    for (int i = 0; i < 16; i++)
        #pragma unroll
        for (int c = 0; c < 4; c++) oacc[i][c] = 0.0f;
    float mprev[2] = {-1e30f, -1e30f};
    float lsum[2]  = {0.0f, 0.0f};

    const int ar = l & 15, asel = l >> 4;
    const int br = ((l >> 4) << 3) + (l & 7), bsel = (l >> 3) & 1;
    const int sw = l & 7;
    const float alpha = 0.08838834764831845f;   // 1/sqrt(128)

    const uint32_t sK = sb + 2 * TILEB;
    const uint32_t sV = sb + 4 * TILEB;

    for (int j = 0; j < 4; j++) {
        cp_wait<0>();
        __syncthreads();               // K/V for step j ready in smem

        // ---- S = Q @ K^T  (16 q-rows x 128 keys per warp)
        float sacc[16][4];
        #pragma unroll
        for (int i = 0; i < 16; i++)
            #pragma unroll
            for (int c = 0; c < 4; c++) sacc[i][c] = 0.0f;

        #pragma unroll
        for (int kp = 0; kp < 8; kp++) {
            uint32_t aq[4];
            uint32_t qa = sb + (kp >> 2) * TILEB + (w * 16 + ar) * 128
                        + ((((kp & 3) * 2 + asel) ^ sw) << 4);
            ldsm4(aq[0], aq[1], aq[2], aq[3], qa);
            #pragma unroll
            for (int nb = 0; nb < 8; nb++) {
                uint32_t b0, b1, b2, b3;
                uint32_t ka = sK + (kp >> 2) * TILEB + (nb * 16 + br) * 128
                            + ((((kp & 3) * 2 + bsel) ^ sw) << 4);
                ldsm4(b0, b1, b2, b3, ka);
                mma16816(sacc[nb * 2],     aq, b0, b1);
                mma16816(sacc[nb * 2 + 1], aq, b2, b3);
            }
        }

        // ---- scale + zero-diagonal (masked BEFORE softmax, value 0)
        #pragma unroll
        for (int i = 0; i < 16; i++)
            #pragma unroll
            for (int c = 0; c < 4; c++) sacc[i][c] *= alpha;
        if (by == j) {
            int r0 = w * 16 + (l >> 2);
            #pragma unroll
            for (int nt = 0; nt < 16; nt++) {
                int cb = nt * 8 + (l & 3) * 2;
                if (cb     == r0)     sacc[nt][0] = 0.0f;
                if (cb + 1 == r0)     sacc[nt][1] = 0.0f;
                if (cb     == r0 + 8) sacc[nt][2] = 0.0f;
                if (cb + 1 == r0 + 8) sacc[nt][3] = 0.0f;
            }
        }

        // ---- online softmax
        #pragma unroll
        for (int g = 0; g < 2; g++) {
            float mx = -1e30f;
            #pragma unroll
            for (int nt = 0; nt < 16; nt++)
                mx = fmaxf(mx, fmaxf(sacc[nt][2 * g], sacc[nt][2 * g + 1]));
            mx = fmaxf(mx, __shfl_xor_sync(0xffffffffu, mx, 1));
            mx = fmaxf(mx, __shfl_xor_sync(0xffffffffu, mx, 2));
            float mnew = fmaxf(mprev[g], mx);
            float sc = __expf(mprev[g] - mnew);
            float sum = 0.0f;
            #pragma unroll
            for (int nt = 0; nt < 16; nt++) {
                float e0 = __expf(sacc[nt][2 * g]     - mnew);
                float e1 = __expf(sacc[nt][2 * g + 1] - mnew);
                sacc[nt][2 * g] = e0; sacc[nt][2 * g + 1] = e1;
                sum += e0 + e1;
            }
            sum += __shfl_xor_sync(0xffffffffu, sum, 1);
            sum += __shfl_xor_sync(0xffffffffu, sum, 2);
            lsum[g] = lsum[g] * sc + sum;
            mprev[g] = mnew;
            #pragma unroll
            for (int nt = 0; nt < 16; nt++) {
                oacc[nt][2 * g]     *= sc;
                oacc[nt][2 * g + 1] *= sc;
            }
        }

        // ---- P: C-layout fp32 -> A-layout fp16
        uint32_t aP[8][4];
        #pragma unroll
        for (int t = 0; t < 8; t++) {
            aP[t][0] = f2h2(sacc[2*t][0],   sacc[2*t][1]);
            aP[t][1] = f2h2(sacc[2*t][2],   sacc[2*t][3]);
            aP[t][2] = f2h2(sacc[2*t+1][0], sacc[2*t+1][1]);
            aP[t][3] = f2h2(sacc[2*t+1][2], sacc[2*t+1][3]);
        }

        // ---- O += P @ V'
        #pragma unroll
        for (int t = 0; t < 8; t++) {
            #pragma unroll
            for (int nb = 0; nb < 8; nb++) {
                uint32_t b0, b1, b2, b3;
                uint32_t va = sV + (t >> 2) * TILEB + (nb * 16 + br) * 128
                            + ((((t & 3) * 2 + bsel) ^ sw) << 4);
                ldsm4(b0, b1, b2, b3, va);
                mma16816(oacc[nb * 2],     aP[t], b0, b1);
                mma16816(oacc[nb * 2 + 1], aP[t], b2, b3);
            }
        }
        __syncthreads();               // all warps done reading K/V

        if (j < 3) {
            const f16* pK = pK0 + (long)(j + 1) * 128 * 3072;
            const f16* pV = pV0 + (j + 1) * 128;
            tile_cp(sK,          pK,      3072, tid);
            tile_cp(sK + TILEB,  pK + 64, 3072, tid);
            tile_cp(sV,          pV,      Mc, tid);
            tile_cp(sV + TILEB,  pV + 64, Mc, tid);
            cp_commit();
        }
    }

    // ---- normalize + store
    #pragma unroll
    for (int g = 0; g < 2; g++) {
        float inv = 1.0f / lsum[g];
        long m = qrow0 + w * 16 + (l >> 2) + 8 * g;
        f16* op = outp + m * Hc + h * HDc + (l & 3) * 2;
        #pragma unroll
        for (int nt = 0; nt < 16; nt++) {
            float v0 = oacc[nt][2 * g] * inv, v1 = oacc[nt][2 * g + 1] * inv;
            *(__half2*)(op + nt * 8) = __halves2half2(__float2half(v0), __float2half(v1));
        }
    }
}

// ---------------------------------------------------------------------------
// Launch
// ---------------------------------------------------------------------------
extern "C" void kernel_launch(void* const* d_in, const int* in_sizes, int n_in,
                              void* d_out, int out_size)
{
    const float* x      = (const float*)d_in[0];
    const float* conv_w = (const float*)d_in[1];
    const float* conv_b = (const float*)d_in[2];
    const float* w1 = (const float*)d_in[3];
    const float* b1 = (const float*)d_in[4];
    const float* w2 = (const float*)d_in[5];
    const float* b2 = (const float*)d_in[6];
    const float* ln_g = (const float*)d_in[7];
    const float* ln_b = (const float*)d_in[8];
    const float* wq = (const float*)d_in[9];
    const float* bq = (const float*)d_in[10];
    const float* wk = (const float*)d_in[11];
    const float* bk = (const float*)d_in[12];
    const float* wv = (const float*)d_in[13];
    const float* bv = (const float*)d_in[14];
    const float* wo = (const float*)d_in[15];
    const float* bo = (const float*)d_in[16];
    const float* wp = (const float*)d_in[17];
    const float* bp = (const float*)d_in[18];
    float* out = (float*)d_out;

    #define SYM(p, s) void* p; cudaGetSymbolAddress(&p, s)
    SYM(xah, g_xah);
    SYM(h1, g_h1);
    SYM(xreg, g_xreg);
    SYM(xnh, g_xnh);
    SYM(qkv, g_qkv); SYM(vth, g_vth);
    SYM(ch, g_ch);
    SYM(w1t, g_w1t); SYM(w2t, g_w2t);
    SYM(wqkv, g_wqkv); SYM(bqkv, g_bqkv);
    SYM(wo16, g_wo16); SYM(wpt, g_wpt); SYM(wopT, g_wopT); SYM(bop, g_bop);
    #undef SYM

    const int SMB_1 = NST * 2 * TILEB;   //  98304
    const int SMB_F = 6 * TILEB;         //  98304
    cudaFuncSetAttribute(mmk<1,3>, cudaFuncAttributeMaxDynamicSharedMemorySize, SMB_1);
    cudaFuncSetAttribute(mmk<0,1>, cudaFuncAttributeMaxDynamicSharedMemorySize, SMB_1);
    cudaFuncSetAttribute(mmk<1,1>, cudaFuncAttributeMaxDynamicSharedMemorySize, SMB_1);
    cudaFuncSetAttribute(mmk<1,0>, cudaFuncAttributeMaxDynamicSharedMemorySize, SMB_1);
    cudaFuncSetAttribute(mmk<0,5>, cudaFuncAttributeMaxDynamicSharedMemorySize, SMB_1);
    cudaFuncSetAttribute(fattn, cudaFuncAttributeMaxDynamicSharedMemorySize, SMB_F);

    const int BMrows = Bc * Mc;  // 32768

    // 1. conv means, affine -> fp16
    means_k<<<1, 1024>>>(conv_w, conv_b);
    affine_k<<<(unsigned)(BMM / 4 / 256), 256>>>((const float4*)x, (f16*)xah);

    // 2. weight prep
    wsplit1<<<dim3(Mc/32, Hc/32), dim3(32,8)>>>(w1, (f16*)w1t, Mc, Hc);
    wsplit1<<<dim3(Hc/32, Hc/32), dim3(32,8)>>>(w2, (f16*)w2t, Hc, Hc);
    wsplit1<<<dim3(Hc/32, Hc/32), dim3(32,8)>>>(wq, (f16*)wqkv,                   Hc, Hc);
    wsplit1<<<dim3(Hc/32, Hc/32), dim3(32,8)>>>(wk, (f16*)wqkv + (size_t)Hc*Hc,   Hc, Hc);
    wsplit1<<<dim3(Hc/32, Hc/32), dim3(32,8)>>>(wv, (f16*)wqkv + (size_t)2*Hc*Hc, Hc, Hc);
    wcast<<<Hc*Hc/4/256, 256>>>((const float4*)wo, (f16*)wo16);
    wsplit1<<<dim3(Hc/32, Hc/32), dim3(32,8)>>>(wp, (f16*)wpt, Hc, Hc);
    bcat<<<12, 256>>>(bq, bk, bv, (float*)bqkv);
    bop_k<<<4, 256>>>(bo, wp, bp, (float*)bop);

    // 3. wopT[n,j] = sum_k wp[k,n]·wo[j,k] = (wo@wp)^T  -> [N,K] for final GEMM
    mmk<1,0><<<dim3(Hc/128, Hc/128, 1), 256, SMB_1>>>(
        (f16*)wpt, (f16*)wo16, nullptr, nullptr, nullptr, (f16*)wopT,
        Hc, Hc, Hc, Hc, 1, 0,0,0,0,0,0, 1.0f);

    // 4. h1 = relu(xa @ w1 + b1) -> fp16
    mmk<1,3><<<dim3(Hc/128, BMrows/128, 1), 256, SMB_1>>>(
        (f16*)xah, (f16*)w1t, b1, nullptr, nullptr, (f16*)h1,
        Mc, Mc, Mc, Hc, 1, 0,0,0,0,0,0, 1.0f);

    // 5. xreg = h1 @ w2 + b2 (fp32)
    mmk<0,1><<<dim3(Hc/128, BMrows/128, 1), 256, SMB_1>>>(
        (f16*)h1, (f16*)w2t, b2, nullptr, (float*)xreg, nullptr,
        Hc, Hc, Hc, Hc, 1, 0,0,0,0,0,0, 1.0f);

    // 6. layernorm -> fp16
    ln_k<<<BMrows, 256>>>((const float*)xreg, ln_g, ln_b, (f16*)xnh);

    // 7. fused q|k|v projection
    mmk<1,1><<<dim3(3*Hc/128, BMrows/128, 1), 256, SMB_1>>>(
        (f16*)xnh, (f16*)wqkv, (const float*)bqkv, nullptr, nullptr, (f16*)qkv,
        Hc, Hc, Hc, 3*Hc, 1, 0,0,0,0,0,0, 1.0f);

    // 8. vT fp16 [B*NH, HD, M]
    vsplitT<<<dim3(Mc/32, HDc/32, Bc*NHc), dim3(32,8)>>>((const f16*)qkv, (f16*)vth);

    // 9. fused attention -> ch
    fattn<<<dim3(Mc/128, Bc*NHc), 256, SMB_F>>>((const f16*)qkv, (const f16*)vth, (f16*)ch);

    // 10. out = ctx @ (wo@wp) + (bo@wp + bp) + xreg (fp32)
    mmk<0,5><<<dim3(Hc/128, BMrows/128, 1), 256, SMB_1>>>(
        (f16*)ch, (f16*)wopT, (const float*)bop, (const float*)xreg, out, nullptr,
        Hc, Hc, Hc, Hc, 1, 0,0,0,0,0,0, 1.0f);
}

// round 16
// speedup vs baseline: 1.1019x; 1.0882x over previous
#include <cuda_runtime.h>
#include <cuda_fp16.h>
#include <cstdint>

#define Bc  64
#define Mc  512
#define Hc  1024
#define NHc 8
#define HDc 128
#define EPSc 1e-5f

typedef __half f16;

#define BMH ((size_t)Bc*Mc*Hc)
#define BMM ((size_t)Bc*Mc*Mc)

// ---------------------------------------------------------------------------
// Scratch (static device globals — allocation-free)
// ---------------------------------------------------------------------------
__device__ float g_mw, g_mb;
__device__ f16 g_xah[BMM];
__device__ f16 g_h1[BMH];
__device__ float g_xreg[BMH];
__device__ f16 g_xnh[BMH];
__device__ f16 g_qkv[(size_t)Bc*Mc*3*Hc];         // [B*M, 3072] = q|k|v
__device__ f16 g_ch[BMH];
// fp16 weights
__device__ f16 g_w1t[(size_t)Hc*Mc];              // [N,K]
__device__ f16 g_w2t[(size_t)Hc*Hc];              // [N,K]
__device__ f16 g_wqkv[(size_t)3*Hc*Hc];           // [3072, 1024]
__device__ f16 g_wo16[(size_t)Hc*Hc];             // wo row-major (untransposed!)
__device__ f16 g_wpt[(size_t)Hc*Hc];              // [N,K]
__device__ f16 g_wopT[(size_t)Hc*Hc];             // (wo@wp)^T in [N,K]
__device__ float g_bqkv[3*Hc];
__device__ float g_bop[Hc];                       // bo@wp + bp

// ---------------------------------------------------------------------------
// PTX helpers (baseline PTX only — no tcgen05 on compute_103)
// ---------------------------------------------------------------------------
__device__ __forceinline__ uint32_t smem_u32(const void* p) {
    uint32_t a;
    asm("{ .reg .u64 t; cvta.to.shared.u64 t, %1; cvt.u32.u64 %0, t; }"
        : "=r"(a) : "l"(p));
    return a;
}

// pack two fp32 -> u32 {hi:f16(hi), lo:f16(lo)}
__device__ __forceinline__ uint32_t f2h2(float lo, float hi) {
    uint32_t r;
    asm("cvt.rn.f16x2.f32 %0, %1, %2;" : "=r"(r) : "f"(hi), "f"(lo));
    return r;
}

__device__ __forceinline__ void cp_async16(uint32_t saddr, const void* gaddr) {
    asm volatile("cp.async.cg.shared.global [%0], [%1], 16;\n"
                 :: "r"(saddr), "l"(gaddr));
}
__device__ __forceinline__ void cp_commit() {
    asm volatile("cp.async.commit_group;\n" ::: "memory");
}
template<int N>
__device__ __forceinline__ void cp_wait() {
    asm volatile("cp.async.wait_group %0;\n" :: "n"(N) : "memory");
}

__device__ __forceinline__ void ldsm4(uint32_t& r0, uint32_t& r1, uint32_t& r2, uint32_t& r3,
                                      uint32_t addr) {
    asm volatile("ldmatrix.sync.aligned.m8n8.x4.shared.b16 {%0,%1,%2,%3}, [%4];"
                 : "=r"(r0), "=r"(r1), "=r"(r2), "=r"(r3) : "r"(addr));
}

__device__ __forceinline__ void ldsm4t(uint32_t& r0, uint32_t& r1, uint32_t& r2, uint32_t& r3,
                                       uint32_t addr) {
    asm volatile("ldmatrix.sync.aligned.m8n8.x4.trans.shared.b16 {%0,%1,%2,%3}, [%4];"
                 : "=r"(r0), "=r"(r1), "=r"(r2), "=r"(r3) : "r"(addr));
}

__device__ __forceinline__ void mma16816(float* c, const uint32_t* a, uint32_t b0, uint32_t b1) {
    asm volatile("mma.sync.aligned.m16n8k16.row.col.f32.f16.f16.f32 "
                 "{%0,%1,%2,%3}, {%4,%5,%6,%7}, {%8,%9}, {%0,%1,%2,%3};"
                 : "+f"(c[0]), "+f"(c[1]), "+f"(c[2]), "+f"(c[3])
                 : "r"(a[0]), "r"(a[1]), "r"(a[2]), "r"(a[3]), "r"(b0), "r"(b1));
}

// ---------------------------------------------------------------------------
// small kernels
// ---------------------------------------------------------------------------
__global__ void means_k(const float* __restrict__ w, const float* __restrict__ b) {
    __shared__ float sw[32], sb[32];
    int t = threadIdx.x;
    float vw = w[t], vb = b[t];
    #pragma unroll
    for (int o = 16; o > 0; o >>= 1) {
        vw += __shfl_down_sync(0xffffffffu, vw, o);
        vb += __shfl_down_sync(0xffffffffu, vb, o);
    }
    if ((t & 31) == 0) { sw[t >> 5] = vw; sb[t >> 5] = vb; }
    __syncthreads();
    if (t < 32) {
        vw = sw[t]; vb = sb[t];
        #pragma unroll
        for (int o = 16; o > 0; o >>= 1) {
            vw += __shfl_down_sync(0xffffffffu, vw, o);
            vb += __shfl_down_sync(0xffffffffu, vb, o);
        }
        if (t == 0) { g_mw = vw / (float)Hc; g_mb = vb / (float)Hc; }
    }
}

__global__ void affine_k(const float4* __restrict__ x, f16* __restrict__ xh) {
    long i = (long)blockIdx.x * blockDim.x + threadIdx.x;
    float a = 1.0f + g_mw, c = g_mb;
    float4 v = x[i];
    ((__half2*)(xh + i * 4))[0] = __halves2half2(__float2half(v.x * a + c), __float2half(v.y * a + c));
    ((__half2*)(xh + i * 4))[1] = __halves2half2(__float2half(v.z * a + c), __float2half(v.w * a + c));
}

// Batched weight transpose: W [K,N] fp32 -> WT fp16 [N,K], 6 weights in one launch
__global__ void wsplit_all(const float* __restrict__ w1, const float* __restrict__ w2,
                           const float* __restrict__ wq, const float* __restrict__ wk,
                           const float* __restrict__ wv, const float* __restrict__ wp,
                           f16* __restrict__ w1t, f16* __restrict__ w2t,
                           f16* __restrict__ wqkv, f16* __restrict__ wpt) {
    const float* W; f16* Th; int K;
    switch (blockIdx.z) {
        case 0:  W = w1; Th = w1t;  K = Mc; break;
        case 1:  W = w2; Th = w2t;  K = Hc; break;
        case 2:  W = wq; Th = wqkv; K = Hc; break;
        case 3:  W = wk; Th = wqkv + (size_t)Hc*Hc;   K = Hc; break;
        case 4:  W = wv; Th = wqkv + (size_t)2*Hc*Hc; K = Hc; break;
        default: W = wp; Th = wpt;  K = Hc; break;
    }
    int k0 = blockIdx.x * 32, n0 = blockIdx.y * 32;
    if (k0 >= K) return;
    __shared__ float t[32][33];
    int tx = threadIdx.x, ty = threadIdx.y;
    #pragma unroll
    for (int i = ty; i < 32; i += 8)
        t[i][tx] = W[(long)(k0 + i) * Hc + n0 + tx];
    __syncthreads();
    #pragma unroll
    for (int i = ty; i < 32; i += 8)
        Th[(long)(n0 + i) * K + k0 + tx] = __float2half(t[tx][i]);
}

// plain fp32 -> fp16 cast (no transpose), 4 elems/thread
__global__ void wcast(const float4* __restrict__ W, f16* __restrict__ o) {
    long i = (long)blockIdx.x * blockDim.x + threadIdx.x;
    float4 v = W[i];
    ((__half2*)(o + i * 4))[0] = __halves2half2(__float2half(v.x), __float2half(v.y));
    ((__half2*)(o + i * 4))[1] = __halves2half2(__float2half(v.z), __float2half(v.w));
}

__global__ void bcat(const float* __restrict__ bq, const float* __restrict__ bk,
                     const float* __restrict__ bv, float* __restrict__ o) {
    int i = blockIdx.x * 256 + threadIdx.x;
    o[i] = i < Hc ? bq[i] : (i < 2 * Hc ? bk[i - Hc] : bv[i - 2 * Hc]);
}

// bop[n] = bp[n] + sum_j bo[j] * wp[j,n]
__global__ void bop_k(const float* __restrict__ bo, const float* __restrict__ wp,
                      const float* __restrict__ bp, float* __restrict__ o) {
    int n = blockIdx.x * 256 + threadIdx.x;
    float s = bp[n];
    for (int j = 0; j < Hc; j++) s += bo[j] * wp[(long)j * Hc + n];
    o[n] = s;
}

__global__ void ln_k(const float* __restrict__ in, const float* __restrict__ g,
                     const float* __restrict__ be, f16* __restrict__ oh) {
    long row = blockIdx.x;
    const float4* p = (const float4*)(in + row * Hc);
    int t = threadIdx.x;
    float4 v = p[t];
    float s  = v.x + v.y + v.z + v.w;
    float s2 = v.x * v.x + v.y * v.y + v.z * v.z + v.w * v.w;
    __shared__ float ss[8], ss2[8];
    #pragma unroll
    for (int of = 16; of > 0; of >>= 1) {
        s  += __shfl_down_sync(0xffffffffu, s, of);
        s2 += __shfl_down_sync(0xffffffffu, s2, of);
    }
    if ((t & 31) == 0) { ss[t >> 5] = s; ss2[t >> 5] = s2; }
    __syncthreads();
    __shared__ float mu_s, ri_s;
    if (t == 0) {
        float a = 0.f, b2 = 0.f;
        #pragma unroll
        for (int i = 0; i < 8; i++) { a += ss[i]; b2 += ss2[i]; }
        float mu = a / (float)Hc;
        mu_s = mu;
        ri_s = rsqrtf(b2 / (float)Hc - mu * mu + EPSc);
    }
    __syncthreads();
    float mu = mu_s, ri = ri_s;
    float4 gv = ((const float4*)g)[t];
    float4 bv = ((const float4*)be)[t];
    long o = row * Hc + t * 4;
    ((__half2*)(oh + o))[0] = __halves2half2(
        __float2half((v.x - mu) * ri * gv.x + bv.x), __float2half((v.y - mu) * ri * gv.y + bv.y));
    ((__half2*)(oh + o))[1] = __halves2half2(
        __float2half((v.z - mu) * ri * gv.z + bv.z), __float2half((v.w - mu) * ri * gv.w + bv.w));
}

// ---------------------------------------------------------------------------
// mma.sync fp16 GEMM (R9 config): C[M,N] = alpha*(A @ B^T) (+bias)(relu)(+res)
//   OUT: 0 = fp32 C, 1 = fp16 Ch.  EPI bits: 1=bias, 2=relu, 4=residual
//   BM=BN=128, BK=64, 256 thr = 8 warps (2x4), warp tile 64x32, 3 stages.
// ---------------------------------------------------------------------------
#define NST 3
#define TILEB 16384                 // one 128x64 fp16 tile

__device__ __forceinline__ void tile_cp(uint32_t sm, const f16* __restrict__ g, long ld, int tid) {
    int r = tid >> 3;
    int c16 = tid & 7;
    const char* gp = (const char*)(g + c16 * 8);
    #pragma unroll
    for (int i = 0; i < 4; i++) {
        int row = r + i * 32;
        uint32_t so = sm + row * 128 + ((c16 ^ (row & 7)) << 4);
        cp_async16(so, gp + (long)row * ld * 2);
    }
}

template<int OUT, int EPI>
__device__ __forceinline__ void store_pair(long off, long c, float v0, float v1,
                                           const float* __restrict__ bias,
                                           const float* __restrict__ Res,
                                           float* __restrict__ C, f16* __restrict__ Ch,
                                           float alpha) {
    v0 *= alpha; v1 *= alpha;
    if (EPI & 1) { v0 += bias[c]; v1 += bias[c + 1]; }
    if (EPI & 2) { v0 = fmaxf(v0, 0.f); v1 = fmaxf(v1, 0.f); }
    if (EPI & 4) {
        float2 rv = *(const float2*)(Res + off);
        v0 += rv.x; v1 += rv.y;
    }
    if (OUT == 0) {
        *(float2*)(C + off) = make_float2(v0, v1);
    } else {
        *(__half2*)(Ch + off) = __halves2half2(__float2half(v0), __float2half(v1));
    }
}

template<int OUT, int EPI>
__global__ void __launch_bounds__(256, 2)
mmk(const f16* __restrict__ Ah, const f16* __restrict__ Bh,
    const float* __restrict__ bias, const float* __restrict__ Res,
    float* __restrict__ C, f16* __restrict__ Ch,
    int Kdim, int lda, int ldb, int ldc,
    int nh, long sA0, long sA1, long sB0, long sB1, long sC0, long sC1,
    float alpha)
{
    extern __shared__ __align__(1024) char smem[];
    constexpr int STAGEB = 2 * TILEB;

    const uint32_t sb = smem_u32(smem);
    const int tid = threadIdx.x;
    const int wid = tid >> 5, l = tid & 31;
    const int wm = wid >> 2, wn = wid & 3;

    const int z = blockIdx.z;
    const long zb = z / nh, zh = z - zb * (long)nh;
    const long row0 = (long)blockIdx.y * 128;
    const long col0 = (long)blockIdx.x * 128;

    const f16* pAh = Ah + zb * sA0 + zh * sA1 + row0 * lda;
    const f16* pBh = Bh + zb * sB0 + zh * sB1 + col0 * ldb;

    float acc[4][4][4];
    #pragma unroll
    for (int i = 0; i < 4; i++)
        #pragma unroll
        for (int j = 0; j < 4; j++)
            #pragma unroll
            for (int r = 0; r < 4; r++) acc[i][j][r] = 0.0f;

    const int nchunk = Kdim >> 6;

    #pragma unroll
    for (int s = 0; s < NST - 1; s++) {
        if (s < nchunk) {
            uint32_t st = sb + s * STAGEB;
            long k0 = (long)s << 6;
            tile_cp(st,         pAh + k0, lda, tid);
            tile_cp(st + TILEB, pBh + k0, ldb, tid);
        }
        cp_commit();
    }

    const int ar = l & 15, asel = l >> 4, swa = l & 7;
    const int br = ((l >> 4) << 3) + (l & 7), bsel = (l >> 3) & 1;
    const int swb = br & 7;

    for (int c = 0; c < nchunk; c++) {
        cp_wait<1>();
        __syncthreads();
        if (c + 2 < nchunk) {
            uint32_t st = sb + ((c + 2) % NST) * STAGEB;
            long k0 = (long)(c + 2) << 6;
            tile_cp(st,         pAh + k0, lda, tid);
            tile_cp(st + TILEB, pBh + k0, ldb, tid);
        }
        cp_commit();

        const uint32_t st = sb + (c % NST) * STAGEB;
        #pragma unroll
        for (int kp = 0; kp < 4; kp++) {
            uint32_t aH[4][4], bH[4][2];
            #pragma unroll
            for (int mt = 0; mt < 4; mt++) {
                int row = wm * 64 + mt * 16 + ar;
                uint32_t ad = st + row * 128 + (((kp * 2 + asel) ^ swa) << 4);
                ldsm4(aH[mt][0], aH[mt][1], aH[mt][2], aH[mt][3], ad);
            }
            #pragma unroll
            for (int np = 0; np < 2; np++) {
                int row = wn * 32 + np * 16 + br;
                uint32_t bd = st + TILEB + row * 128 + (((kp * 2 + bsel) ^ swb) << 4);
                ldsm4(bH[np*2][0], bH[np*2][1], bH[np*2+1][0], bH[np*2+1][1], bd);
            }
            #pragma unroll
            for (int mt = 0; mt < 4; mt++)
                #pragma unroll
                for (int nt = 0; nt < 4; nt++)
                    mma16816(acc[mt][nt], aH[mt], bH[nt][0], bH[nt][1]);
        }
        __syncthreads();
    }

    const long Rw = row0 + wm * 64;
    const long Cw = col0 + wn * 32;
    const long base = zb * sC0 + zh * sC1;
    const int lr = l >> 2, lc = (l & 3) * 2;
    #pragma unroll
    for (int mt = 0; mt < 4; mt++) {
        long r0 = Rw + mt * 16 + lr;
        #pragma unroll
        for (int nt = 0; nt < 4; nt++) {
            long cc = Cw + nt * 8 + lc;
            store_pair<OUT, EPI>(base + r0 * ldc + cc, cc, acc[mt][nt][0], acc[mt][nt][1],
                                 bias, Res, C, Ch, alpha);
            store_pair<OUT, EPI>(base + (r0 + 8) * ldc + cc, cc, acc[mt][nt][2], acc[mt][nt][3],
                                 bias, Res, C, Ch, alpha);
        }
    }
}

// ---------------------------------------------------------------------------
// Fused attention (R9 double-buffered pipeline) with direct-V via ldmatrix.trans.
//   per CTA = one 128-row q-tile of one (b,h); 8 warps, 16 q-rows each.
//   V read straight from qkv's v-slice (row-major [key, d]); the P@V B-operand
//   is produced by ldmatrix.x4.trans — no vT buffer, no vsplitT pass.
// smem: Q[2] | buf0: K[2] V[2] | buf1: K[2] V[2]  = 10 * TILEB = 160 KB
// ---------------------------------------------------------------------------
__global__ void __launch_bounds__(256, 1)
fattn(const f16* __restrict__ qkv, f16* __restrict__ outp)
{
    extern __shared__ __align__(1024) char smem[];
    const uint32_t sb = smem_u32(smem);
    const int tid = threadIdx.x;
    const int w = tid >> 5, l = tid & 31;
    const int by = blockIdx.x;                 // q-tile 0..3
    const int z  = blockIdx.y;                 // b*8 + h
    const int b = z >> 3, h = z & 7;

    const long qrow0 = (long)b * Mc + by * 128;
    const f16* pQ  = qkv + qrow0 * 3072 + h * HDc;
    const f16* pK0 = qkv + (long)b * Mc * 3072 + Hc + h * HDc;
    const f16* pV0 = qkv + (long)b * Mc * 3072 + 2 * Hc + h * HDc;

    // prologue: Q (2 subtiles) + K0/V0 into buffer 0. V rows = keys, ld=3072.
    tile_cp(sb + 0 * TILEB, pQ,       3072, tid);
    tile_cp(sb + 1 * TILEB, pQ + 64,  3072, tid);
    tile_cp(sb + 2 * TILEB, pK0,      3072, tid);
    tile_cp(sb + 3 * TILEB, pK0 + 64, 3072, tid);
    tile_cp(sb + 4 * TILEB, pV0,      3072, tid);
    tile_cp(sb + 5 * TILEB, pV0 + 64, 3072, tid);
    cp_commit();

    float oacc[16][4];
    #pragma unroll
    for (int i = 0; i < 16; i++)
        #pragma unroll
        for (int c = 0; c < 4; c++) oacc[i][c] = 0.0f;
    float mprev[2] = {-1e30f, -1e30f};
    float lsum[2]  = {0.0f, 0.0f};

    const int ar = l & 15, asel = l >> 4;
    const int br = ((l >> 4) << 3) + (l & 7), bsel = (l >> 3) & 1;
    const int sw = l & 7;
    // trans-V lane mapping: lanes 0-7 (k0-7,d0-7), 8-15 (k8-15,d0-7),
    //                       16-23 (k0-7,d8-15), 24-31 (k8-15,d8-15)
    const int vkr = ((l >> 3) & 1) * 8 + (l & 7);   // key-row within 16-chunk
    const int vcg = l >> 4;                          // d col-group (0/1)
    const float alpha = 0.08838834764831845f;        // 1/sqrt(128)

    for (int j = 0; j < 4; j++) {
        const int buf = j & 1;
        if (j < 3) {
            const int nb_ = buf ^ 1;
            const f16* pK = pK0 + (long)(j + 1) * 128 * 3072;
            const f16* pV = pV0 + (long)(j + 1) * 128 * 3072;
            tile_cp(sb + (2 + nb_ * 4 + 0) * TILEB, pK,      3072, tid);
            tile_cp(sb + (2 + nb_ * 4 + 1) * TILEB, pK + 64, 3072, tid);
            tile_cp(sb + (2 + nb_ * 4 + 2) * TILEB, pV,      3072, tid);
            tile_cp(sb + (2 + nb_ * 4 + 3) * TILEB, pV + 64, 3072, tid);
            cp_commit();
            cp_wait<1>();
        } else {
            cp_wait<0>();
        }
        __syncthreads();

        const uint32_t sK = sb + (2 + buf * 4) * TILEB;
        const uint32_t sV = sK + 2 * TILEB;

        // ---- S = Q @ K^T  (16 q-rows x 128 keys per warp)
        float sacc[16][4];
        #pragma unroll
        for (int i = 0; i < 16; i++)
            #pragma unroll
            for (int c = 0; c < 4; c++) sacc[i][c] = 0.0f;

        #pragma unroll
        for (int kp = 0; kp < 8; kp++) {
            uint32_t aq[4];
            uint32_t qa = sb + (kp >> 2) * TILEB + (w * 16 + ar) * 128
                        + ((((kp & 3) * 2 + asel) ^ sw) << 4);
            ldsm4(aq[0], aq[1], aq[2], aq[3], qa);
            #pragma unroll
            for (int nb = 0; nb < 8; nb++) {
                uint32_t b0, b1, b2, b3;
                uint32_t ka = sK + (kp >> 2) * TILEB + (nb * 16 + br) * 128
                            + ((((kp & 3) * 2 + bsel) ^ sw) << 4);
                ldsm4(b0, b1, b2, b3, ka);
                mma16816(sacc[nb * 2],     aq, b0, b1);
                mma16816(sacc[nb * 2 + 1], aq, b2, b3);
            }
        }

        // ---- scale + zero-diagonal (masked BEFORE softmax, value 0)
        #pragma unroll
        for (int i = 0; i < 16; i++)
            #pragma unroll
            for (int c = 0; c < 4; c++) sacc[i][c] *= alpha;
        if (by == j) {
            int r0 = w * 16 + (l >> 2);
            #pragma unroll
            for (int nt = 0; nt < 16; nt++) {
                int cb = nt * 8 + (l & 3) * 2;
                if (cb     == r0)     sacc[nt][0] = 0.0f;
                if (cb + 1 == r0)     sacc[nt][1] = 0.0f;
                if (cb     == r0 + 8) sacc[nt][2] = 0.0f;
                if (cb + 1 == r0 + 8) sacc[nt][3] = 0.0f;
            }
        }

        // ---- online softmax
        #pragma unroll
        for (int g = 0; g < 2; g++) {
            float mx = -1e30f;
            #pragma unroll
            for (int nt = 0; nt < 16; nt++)
                mx = fmaxf(mx, fmaxf(sacc[nt][2 * g], sacc[nt][2 * g + 1]));
            mx = fmaxf(mx, __shfl_xor_sync(0xffffffffu, mx, 1));
            mx = fmaxf(mx, __shfl_xor_sync(0xffffffffu, mx, 2));
            float mnew = fmaxf(mprev[g], mx);
            float sc = __expf(mprev[g] - mnew);
            float sum = 0.0f;
            #pragma unroll
            for (int nt = 0; nt < 16; nt++) {
                float e0 = __expf(sacc[nt][2 * g]     - mnew);
                float e1 = __expf(sacc[nt][2 * g + 1] - mnew);
                sacc[nt][2 * g] = e0; sacc[nt][2 * g + 1] = e1;
                sum += e0 + e1;
            }
            sum += __shfl_xor_sync(0xffffffffu, sum, 1);
            sum += __shfl_xor_sync(0xffffffffu, sum, 2);
            lsum[g] = lsum[g] * sc + sum;
            mprev[g] = mnew;
            #pragma unroll
            for (int nt = 0; nt < 16; nt++) {
                oacc[nt][2 * g]     *= sc;
                oacc[nt][2 * g + 1] *= sc;
            }
        }

        // ---- P: C-layout fp32 -> A-layout fp16
        uint32_t aP[8][4];
        #pragma unroll
        for (int t = 0; t < 8; t++) {
            aP[t][0] = f2h2(sacc[2*t][0],   sacc[2*t][1]);
            aP[t][1] = f2h2(sacc[2*t][2],   sacc[2*t][3]);
            aP[t][2] = f2h2(sacc[2*t+1][0], sacc[2*t+1][1]);
            aP[t][3] = f2h2(sacc[2*t+1][2], sacc[2*t+1][3]);
        }

        // ---- O += P @ V, V row-major [key, d] via ldmatrix.trans
        #pragma unroll
        for (int t = 0; t < 8; t++) {
            int vrow = t * 16 + vkr;
            #pragma unroll
            for (int nb = 0; nb < 8; nb++) {
                uint32_t b0, b1, b2, b3;
                uint32_t va = sV + (nb >> 2) * TILEB + vrow * 128
                            + (((((nb & 3) * 2) + vcg) ^ (vrow & 7)) << 4);
                ldsm4t(b0, b1, b2, b3, va);
                mma16816(oacc[nb * 2],     aP[t], b0, b1);
                mma16816(oacc[nb * 2 + 1], aP[t], b2, b3);
            }
        }
        __syncthreads();
    }

    // ---- normalize + store (heads interleaved into [B*M, H])
    #pragma unroll
    for (int g = 0; g < 2; g++) {
        float inv = 1.0f / lsum[g];
        long m = qrow0 + w * 16 + (l >> 2) + 8 * g;
        f16* op = outp + m * Hc + h * HDc + (l & 3) * 2;
        #pragma unroll
        for (int nt = 0; nt < 16; nt++) {
            float v0 = oacc[nt][2 * g] * inv, v1 = oacc[nt][2 * g + 1] * inv;
            *(__half2*)(op + nt * 8) = __halves2half2(__float2half(v0), __float2half(v1));
        }
    }
}

// ---------------------------------------------------------------------------
// Launch
// ---------------------------------------------------------------------------
extern "C" void kernel_launch(void* const* d_in, const int* in_sizes, int n_in,
                              void* d_out, int out_size)
{
    const float* x      = (const float*)d_in[0];
    const float* conv_w = (const float*)d_in[1];
    const float* conv_b = (const float*)d_in[2];
    const float* w1 = (const float*)d_in[3];
    const float* b1 = (const float*)d_in[4];
    const float* w2 = (const float*)d_in[5];
    const float* b2 = (const float*)d_in[6];
    const float* ln_g = (const float*)d_in[7];
    const float* ln_b = (const float*)d_in[8];
    const float* wq = (const float*)d_in[9];
    const float* bq = (const float*)d_in[10];
    const float* wk = (const float*)d_in[11];
    const float* bk = (const float*)d_in[12];
    const float* wv = (const float*)d_in[13];
    const float* bv = (const float*)d_in[14];
    const float* wo = (const float*)d_in[15];
    const float* bo = (const float*)d_in[16];
    const float* wp = (const float*)d_in[17];
    const float* bp = (const float*)d_in[18];
    float* out = (float*)d_out;

    #define SYM(p, s) void* p; cudaGetSymbolAddress(&p, s)
    SYM(xah, g_xah);
    SYM(h1, g_h1);
    SYM(xreg, g_xreg);
    SYM(xnh, g_xnh);
    SYM(qkv, g_qkv);
    SYM(ch, g_ch);
    SYM(w1t, g_w1t); SYM(w2t, g_w2t);
    SYM(wqkv, g_wqkv); SYM(bqkv, g_bqkv);
    SYM(wo16, g_wo16); SYM(wpt, g_wpt); SYM(wopT, g_wopT); SYM(bop, g_bop);
    #undef SYM

    const int SMB_1 = NST * 2 * TILEB;   //  98304
    const int SMB_F = 10 * TILEB;        // 163840
    cudaFuncSetAttribute(mmk<1,3>, cudaFuncAttributeMaxDynamicSharedMemorySize, SMB_1);
    cudaFuncSetAttribute(mmk<0,1>, cudaFuncAttributeMaxDynamicSharedMemorySize, SMB_1);
    cudaFuncSetAttribute(mmk<1,1>, cudaFuncAttributeMaxDynamicSharedMemorySize, SMB_1);
    cudaFuncSetAttribute(mmk<1,0>, cudaFuncAttributeMaxDynamicSharedMemorySize, SMB_1);
    cudaFuncSetAttribute(mmk<0,5>, cudaFuncAttributeMaxDynamicSharedMemorySize, SMB_1);
    cudaFuncSetAttribute(fattn, cudaFuncAttributeMaxDynamicSharedMemorySize, SMB_F);

    const int BMrows = Bc * Mc;  // 32768

    // 1. conv means, affine -> fp16
    means_k<<<1, 1024>>>(conv_w, conv_b);
    affine_k<<<(unsigned)(BMM / 4 / 256), 256>>>((const float4*)x, (f16*)xah);

    // 2. weight prep: one batched transpose launch + cast + fused biases
    wsplit_all<<<dim3(32, 32, 6), dim3(32, 8)>>>(
        w1, w2, wq, wk, wv, wp, (f16*)w1t, (f16*)w2t, (f16*)wqkv, (f16*)wpt);
    wcast<<<Hc*Hc/4/256, 256>>>((const float4*)wo, (f16*)wo16);
    bcat<<<12, 256>>>(bq, bk, bv, (float*)bqkv);
    bop_k<<<4, 256>>>(bo, wp, bp, (float*)bop);

    // 3. wopT[n,j] = sum_k wp[k,n]·wo[j,k] = (wo@wp)^T  -> [N,K] for final GEMM
    mmk<1,0><<<dim3(Hc/128, Hc/128, 1), 256, SMB_1>>>(
        (f16*)wpt, (f16*)wo16, nullptr, nullptr, nullptr, (f16*)wopT,
        Hc, Hc, Hc, Hc, 1, 0,0,0,0,0,0, 1.0f);

    // 4. h1 = relu(xa @ w1 + b1) -> fp16
    mmk<1,3><<<dim3(Hc/128, BMrows/128, 1), 256, SMB_1>>>(
        (f16*)xah, (f16*)w1t, b1, nullptr, nullptr, (f16*)h1,
        Mc, Mc, Mc, Hc, 1, 0,0,0,0,0,0, 1.0f);

    // 5. xreg = h1 @ w2 + b2 (fp32)
    mmk<0,1><<<dim3(Hc/128, BMrows/128, 1), 256, SMB_1>>>(
        (f16*)h1, (f16*)w2t, b2, nullptr, (float*)xreg, nullptr,
        Hc, Hc, Hc, Hc, 1, 0,0,0,0,0,0, 1.0f);

    // 6. layernorm -> fp16
    ln_k<<<BMrows, 256>>>((const float*)xreg, ln_g, ln_b, (f16*)xnh);

    // 7. fused q|k|v projection
    mmk<1,1><<<dim3(3*Hc/128, BMrows/128, 1), 256, SMB_1>>>(
        (f16*)xnh, (f16*)wqkv, (const float*)bqkv, nullptr, nullptr, (f16*)qkv,
        Hc, Hc, Hc, 3*Hc, 1, 0,0,0,0,0,0, 1.0f);

    // 8. fused attention (direct V, no transpose pass) -> ch
    fattn<<<dim3(Mc/128, Bc*NHc), 256, SMB_F>>>((const f16*)qkv, (f16*)ch);

    // 9. out = ctx @ (wo@wp) + (bo@wp + bp) + xreg (fp32)
    mmk<0,5><<<dim3(Hc/128, BMrows/128, 1), 256, SMB_1>>>(
        (f16*)ch, (f16*)wopT, (const float*)bop, (const float*)xreg, out, nullptr,
        Hc, Hc, Hc, Hc, 1, 0,0,0,0,0,0, 1.0f);
}

// round 17
// speedup vs baseline: 1.1116x; 1.0088x over previous
#include <cuda_runtime.h>
#include <cuda_fp16.h>
#include <cstdint>

#define Bc  64
#define Mc  512
#define Hc  1024
#define NHc 8
#define HDc 128
#define EPSc 1e-5f

typedef __half f16;

#define BMH ((size_t)Bc*Mc*Hc)
#define BMM ((size_t)Bc*Mc*Mc)

// ---------------------------------------------------------------------------
// Scratch (static device globals — allocation-free)
// ---------------------------------------------------------------------------
__device__ float g_mw, g_mb;
__device__ f16 g_xah[BMM];
__device__ f16 g_h1[BMH];
__device__ float g_xreg[BMH];
__device__ f16 g_xnh[BMH];
__device__ f16 g_qkv[(size_t)Bc*Mc*3*Hc];         // [B*M, 3072] = q|k|v
__device__ f16 g_ch[BMH];
// fp16 weights
__device__ f16 g_w1t[(size_t)Hc*Mc];              // [N,K]
__device__ f16 g_w2t[(size_t)Hc*Hc];              // [N,K]
__device__ f16 g_wqkv[(size_t)3*Hc*Hc];           // [3072, 1024]
__device__ f16 g_wo16[(size_t)Hc*Hc];             // wo row-major (untransposed!)
__device__ f16 g_wpt[(size_t)Hc*Hc];              // [N,K]
__device__ f16 g_wopT[(size_t)Hc*Hc];             // (wo@wp)^T in [N,K]
__device__ float g_bqkv[3*Hc];
__device__ float g_bop[Hc];                       // bo@wp + bp

// ---------------------------------------------------------------------------
// PTX helpers (baseline PTX only — no tcgen05 on compute_103)
// ---------------------------------------------------------------------------
__device__ __forceinline__ uint32_t smem_u32(const void* p) {
    uint32_t a;
    asm("{ .reg .u64 t; cvta.to.shared.u64 t, %1; cvt.u32.u64 %0, t; }"
        : "=r"(a) : "l"(p));
    return a;
}

// pack two fp32 -> u32 {hi:f16(hi), lo:f16(lo)}
__device__ __forceinline__ uint32_t f2h2(float lo, float hi) {
    uint32_t r;
    asm("cvt.rn.f16x2.f32 %0, %1, %2;" : "=r"(r) : "f"(hi), "f"(lo));
    return r;
}

__device__ __forceinline__ void cp_async16(uint32_t saddr, const void* gaddr) {
    asm volatile("cp.async.cg.shared.global [%0], [%1], 16;\n"
                 :: "r"(saddr), "l"(gaddr));
}
__device__ __forceinline__ void cp_commit() {
    asm volatile("cp.async.commit_group;\n" ::: "memory");
}
template<int N>
__device__ __forceinline__ void cp_wait() {
    asm volatile("cp.async.wait_group %0;\n" :: "n"(N) : "memory");
}

__device__ __forceinline__ void ldsm4(uint32_t& r0, uint32_t& r1, uint32_t& r2, uint32_t& r3,
                                      uint32_t addr) {
    asm volatile("ldmatrix.sync.aligned.m8n8.x4.shared.b16 {%0,%1,%2,%3}, [%4];"
                 : "=r"(r0), "=r"(r1), "=r"(r2), "=r"(r3) : "r"(addr));
}

__device__ __forceinline__ void ldsm4t(uint32_t& r0, uint32_t& r1, uint32_t& r2, uint32_t& r3,
                                       uint32_t addr) {
    asm volatile("ldmatrix.sync.aligned.m8n8.x4.trans.shared.b16 {%0,%1,%2,%3}, [%4];"
                 : "=r"(r0), "=r"(r1), "=r"(r2), "=r"(r3) : "r"(addr));
}

__device__ __forceinline__ void mma16816(float* c, const uint32_t* a, uint32_t b0, uint32_t b1) {
    asm volatile("mma.sync.aligned.m16n8k16.row.col.f32.f16.f16.f32 "
                 "{%0,%1,%2,%3}, {%4,%5,%6,%7}, {%8,%9}, {%0,%1,%2,%3};"
                 : "+f"(c[0]), "+f"(c[1]), "+f"(c[2]), "+f"(c[3])
                 : "r"(a[0]), "r"(a[1]), "r"(a[2]), "r"(a[3]), "r"(b0), "r"(b1));
}

// ---------------------------------------------------------------------------
// small kernels
// ---------------------------------------------------------------------------
__global__ void means_k(const float* __restrict__ w, const float* __restrict__ b) {
    __shared__ float sw[32], sb[32];
    int t = threadIdx.x;
    float vw = w[t], vb = b[t];
    #pragma unroll
    for (int o = 16; o > 0; o >>= 1) {
        vw += __shfl_down_sync(0xffffffffu, vw, o);
        vb += __shfl_down_sync(0xffffffffu, vb, o);
    }
    if ((t & 31) == 0) { sw[t >> 5] = vw; sb[t >> 5] = vb; }
    __syncthreads();
    if (t < 32) {
        vw = sw[t]; vb = sb[t];
        #pragma unroll
        for (int o = 16; o > 0; o >>= 1) {
            vw += __shfl_down_sync(0xffffffffu, vw, o);
            vb += __shfl_down_sync(0xffffffffu, vb, o);
        }
        if (t == 0) { g_mw = vw / (float)Hc; g_mb = vb / (float)Hc; }
    }
}

__global__ void affine_k(const float4* __restrict__ x, f16* __restrict__ xh) {
    long i = (long)blockIdx.x * blockDim.x + threadIdx.x;
    float a = 1.0f + g_mw, c = g_mb;
    float4 v = x[i];
    ((__half2*)(xh + i * 4))[0] = __halves2half2(__float2half(v.x * a + c), __float2half(v.y * a + c));
    ((__half2*)(xh + i * 4))[1] = __halves2half2(__float2half(v.z * a + c), __float2half(v.w * a + c));
}

// Batched weight transpose: W [K,N] fp32 -> WT fp16 [N,K], 6 weights in one launch
__global__ void wsplit_all(const float* __restrict__ w1, const float* __restrict__ w2,
                           const float* __restrict__ wq, const float* __restrict__ wk,
                           const float* __restrict__ wv, const float* __restrict__ wp,
                           f16* __restrict__ w1t, f16* __restrict__ w2t,
                           f16* __restrict__ wqkv, f16* __restrict__ wpt) {
    const float* W; f16* Th; int K;
    switch (blockIdx.z) {
        case 0:  W = w1; Th = w1t;  K = Mc; break;
        case 1:  W = w2; Th = w2t;  K = Hc; break;
        case 2:  W = wq; Th = wqkv; K = Hc; break;
        case 3:  W = wk; Th = wqkv + (size_t)Hc*Hc;   K = Hc; break;
        case 4:  W = wv; Th = wqkv + (size_t)2*Hc*Hc; K = Hc; break;
        default: W = wp; Th = wpt;  K = Hc; break;
    }
    int k0 = blockIdx.x * 32, n0 = blockIdx.y * 32;
    if (k0 >= K) return;
    __shared__ float t[32][33];
    int tx = threadIdx.x, ty = threadIdx.y;
    #pragma unroll
    for (int i = ty; i < 32; i += 8)
        t[i][tx] = W[(long)(k0 + i) * Hc + n0 + tx];
    __syncthreads();
    #pragma unroll
    for (int i = ty; i < 32; i += 8)
        Th[(long)(n0 + i) * K + k0 + tx] = __float2half(t[tx][i]);
}

// Merged prep: wo fp32->fp16 cast (blocks 0..1023), bias concat (1024..1035),
// bop = bo@wp + bp (1036..1039). One launch instead of three.
__global__ void prep_k(const float4* __restrict__ wo, f16* __restrict__ wo16,
                       const float* __restrict__ bq, const float* __restrict__ bk,
                       const float* __restrict__ bv, float* __restrict__ bqkv,
                       const float* __restrict__ bo, const float* __restrict__ wp,
                       const float* __restrict__ bp, float* __restrict__ bop) {
    int bx = blockIdx.x, t = threadIdx.x;
    if (bx < 1024) {                       // wcast: 1024*256 float4 = Hc*Hc
        long i = (long)bx * 256 + t;
        float4 v = wo[i];
        ((__half2*)(wo16 + i * 4))[0] = __halves2half2(__float2half(v.x), __float2half(v.y));
        ((__half2*)(wo16 + i * 4))[1] = __halves2half2(__float2half(v.z), __float2half(v.w));
    } else if (bx < 1036) {                // bcat: 12*256 = 3072
        int i = (bx - 1024) * 256 + t;
        bqkv[i] = i < Hc ? bq[i] : (i < 2 * Hc ? bk[i - Hc] : bv[i - 2 * Hc]);
    } else {                               // bop: 4*256 = 1024
        int n = (bx - 1036) * 256 + t;
        float s = bp[n];
        for (int j = 0; j < Hc; j++) s += bo[j] * wp[(long)j * Hc + n];
        bop[n] = s;
    }
}

__global__ void ln_k(const float* __restrict__ in, const float* __restrict__ g,
                     const float* __restrict__ be, f16* __restrict__ oh) {
    long row = blockIdx.x;
    const float4* p = (const float4*)(in + row * Hc);
    int t = threadIdx.x;
    float4 v = p[t];
    float s  = v.x + v.y + v.z + v.w;
    float s2 = v.x * v.x + v.y * v.y + v.z * v.z + v.w * v.w;
    __shared__ float ss[8], ss2[8];
    #pragma unroll
    for (int of = 16; of > 0; of >>= 1) {
        s  += __shfl_down_sync(0xffffffffu, s, of);
        s2 += __shfl_down_sync(0xffffffffu, s2, of);
    }
    if ((t & 31) == 0) { ss[t >> 5] = s; ss2[t >> 5] = s2; }
    __syncthreads();
    __shared__ float mu_s, ri_s;
    if (t == 0) {
        float a = 0.f, b2 = 0.f;
        #pragma unroll
        for (int i = 0; i < 8; i++) { a += ss[i]; b2 += ss2[i]; }
        float mu = a / (float)Hc;
        mu_s = mu;
        ri_s = rsqrtf(b2 / (float)Hc - mu * mu + EPSc);
    }
    __syncthreads();
    float mu = mu_s, ri = ri_s;
    float4 gv = ((const float4*)g)[t];
    float4 bv = ((const float4*)be)[t];
    long o = row * Hc + t * 4;
    ((__half2*)(oh + o))[0] = __halves2half2(
        __float2half((v.x - mu) * ri * gv.x + bv.x), __float2half((v.y - mu) * ri * gv.y + bv.y));
    ((__half2*)(oh + o))[1] = __halves2half2(
        __float2half((v.z - mu) * ri * gv.z + bv.z), __float2half((v.w - mu) * ri * gv.w + bv.w));
}

// ---------------------------------------------------------------------------
// mma.sync fp16 GEMM (R9 config): C[M,N] = alpha*(A @ B^T) (+bias)(relu)(+res)
//   OUT: 0 = fp32 C, 1 = fp16 Ch.  EPI bits: 1=bias, 2=relu, 4=residual
//   BM=BN=128, BK=64, 256 thr = 8 warps (2x4), warp tile 64x32, 3 stages.
//   Single barrier per chunk: with 3 stages, iter c+1's loads target stage
//   (c+3)%3 = c%3, and the leading barrier at c+1 already orders them after
//   all reads of stage c — the trailing barrier was redundant.
// ---------------------------------------------------------------------------
#define NST 3
#define TILEB 16384                 // one 128x64 fp16 tile

__device__ __forceinline__ void tile_cp(uint32_t sm, const f16* __restrict__ g, long ld, int tid) {
    int r = tid >> 3;
    int c16 = tid & 7;
    const char* gp = (const char*)(g + c16 * 8);
    #pragma unroll
    for (int i = 0; i < 4; i++) {
        int row = r + i * 32;
        uint32_t so = sm + row * 128 + ((c16 ^ (row & 7)) << 4);
        cp_async16(so, gp + (long)row * ld * 2);
    }
}

template<int OUT, int EPI>
__device__ __forceinline__ void store_pair(long off, long c, float v0, float v1,
                                           const float* __restrict__ bias,
                                           const float* __restrict__ Res,
                                           float* __restrict__ C, f16* __restrict__ Ch,
                                           float alpha) {
    v0 *= alpha; v1 *= alpha;
    if (EPI & 1) { v0 += bias[c]; v1 += bias[c + 1]; }
    if (EPI & 2) { v0 = fmaxf(v0, 0.f); v1 = fmaxf(v1, 0.f); }
    if (EPI & 4) {
        float2 rv = *(const float2*)(Res + off);
        v0 += rv.x; v1 += rv.y;
    }
    if (OUT == 0) {
        *(float2*)(C + off) = make_float2(v0, v1);
    } else {
        *(__half2*)(Ch + off) = __halves2half2(__float2half(v0), __float2half(v1));
    }
}

template<int OUT, int EPI>
__global__ void __launch_bounds__(256, 2)
mmk(const f16* __restrict__ Ah, const f16* __restrict__ Bh,
    const float* __restrict__ bias, const float* __restrict__ Res,
    float* __restrict__ C, f16* __restrict__ Ch,
    int Kdim, int lda, int ldb, int ldc,
    int nh, long sA0, long sA1, long sB0, long sB1, long sC0, long sC1,
    float alpha)
{
    extern __shared__ __align__(1024) char smem[];
    constexpr int STAGEB = 2 * TILEB;

    const uint32_t sb = smem_u32(smem);
    const int tid = threadIdx.x;
    const int wid = tid >> 5, l = tid & 31;
    const int wm = wid >> 2, wn = wid & 3;

    const int z = blockIdx.z;
    const long zb = z / nh, zh = z - zb * (long)nh;
    const long row0 = (long)blockIdx.y * 128;
    const long col0 = (long)blockIdx.x * 128;

    const f16* pAh = Ah + zb * sA0 + zh * sA1 + row0 * lda;
    const f16* pBh = Bh + zb * sB0 + zh * sB1 + col0 * ldb;

    float acc[4][4][4];
    #pragma unroll
    for (int i = 0; i < 4; i++)
        #pragma unroll
        for (int j = 0; j < 4; j++)
            #pragma unroll
            for (int r = 0; r < 4; r++) acc[i][j][r] = 0.0f;

    const int nchunk = Kdim >> 6;

    #pragma unroll
    for (int s = 0; s < NST - 1; s++) {
        if (s < nchunk) {
            uint32_t st = sb + s * STAGEB;
            long k0 = (long)s << 6;
            tile_cp(st,         pAh + k0, lda, tid);
            tile_cp(st + TILEB, pBh + k0, ldb, tid);
        }
        cp_commit();
    }

    const int ar = l & 15, asel = l >> 4, swa = l & 7;
    const int br = ((l >> 4) << 3) + (l & 7), bsel = (l >> 3) & 1;
    const int swb = br & 7;

    for (int c = 0; c < nchunk; c++) {
        cp_wait<1>();
        __syncthreads();
        if (c + 2 < nchunk) {
            uint32_t st = sb + ((c + 2) % NST) * STAGEB;
            long k0 = (long)(c + 2) << 6;
            tile_cp(st,         pAh + k0, lda, tid);
            tile_cp(st + TILEB, pBh + k0, ldb, tid);
        }
        cp_commit();

        const uint32_t st = sb + (c % NST) * STAGEB;
        #pragma unroll
        for (int kp = 0; kp < 4; kp++) {
            uint32_t aH[4][4], bH[4][2];
            #pragma unroll
            for (int mt = 0; mt < 4; mt++) {
                int row = wm * 64 + mt * 16 + ar;
                uint32_t ad = st + row * 128 + (((kp * 2 + asel) ^ swa) << 4);
                ldsm4(aH[mt][0], aH[mt][1], aH[mt][2], aH[mt][3], ad);
            }
            #pragma unroll
            for (int np = 0; np < 2; np++) {
                int row = wn * 32 + np * 16 + br;
                uint32_t bd = st + TILEB + row * 128 + (((kp * 2 + bsel) ^ swb) << 4);
                ldsm4(bH[np*2][0], bH[np*2][1], bH[np*2+1][0], bH[np*2+1][1], bd);
            }
            #pragma unroll
            for (int mt = 0; mt < 4; mt++)
                #pragma unroll
                for (int nt = 0; nt < 4; nt++)
                    mma16816(acc[mt][nt], aH[mt], bH[nt][0], bH[nt][1]);
        }
        // trailing __syncthreads removed: next overwrite of this stage is
        // ordered by the leading barrier of iteration c+1 (3-stage distance).
    }

    const long Rw = row0 + wm * 64;
    const long Cw = col0 + wn * 32;
    const long base = zb * sC0 + zh * sC1;
    const int lr = l >> 2, lc = (l & 3) * 2;
    #pragma unroll
    for (int mt = 0; mt < 4; mt++) {
        long r0 = Rw + mt * 16 + lr;
        #pragma unroll
        for (int nt = 0; nt < 4; nt++) {
            long cc = Cw + nt * 8 + lc;
            store_pair<OUT, EPI>(base + r0 * ldc + cc, cc, acc[mt][nt][0], acc[mt][nt][1],
                                 bias, Res, C, Ch, alpha);
            store_pair<OUT, EPI>(base + (r0 + 8) * ldc + cc, cc, acc[mt][nt][2], acc[mt][nt][3],
                                 bias, Res, C, Ch, alpha);
        }
    }
}

// ---------------------------------------------------------------------------
// Fused attention (R16): double-buffered, direct-V via ldmatrix.trans.
//   per CTA = one 128-row q-tile of one (b,h); 8 warps, 16 q-rows each.
// smem: Q[2] | buf0: K[2] V[2] | buf1: K[2] V[2]  = 10 * TILEB = 160 KB
// ---------------------------------------------------------------------------
__global__ void __launch_bounds__(256, 1)
fattn(const f16* __restrict__ qkv, f16* __restrict__ outp)
{
    extern __shared__ __align__(1024) char smem[];
    const uint32_t sb = smem_u32(smem);
    const int tid = threadIdx.x;
    const int w = tid >> 5, l = tid & 31;
    const int by = blockIdx.x;                 // q-tile 0..3
    const int z  = blockIdx.y;                 // b*8 + h
    const int b = z >> 3, h = z & 7;

    const long qrow0 = (long)b * Mc + by * 128;
    const f16* pQ  = qkv + qrow0 * 3072 + h * HDc;
    const f16* pK0 = qkv + (long)b * Mc * 3072 + Hc + h * HDc;
    const f16* pV0 = qkv + (long)b * Mc * 3072 + 2 * Hc + h * HDc;

    tile_cp(sb + 0 * TILEB, pQ,       3072, tid);
    tile_cp(sb + 1 * TILEB, pQ + 64,  3072, tid);
    tile_cp(sb + 2 * TILEB, pK0,      3072, tid);
    tile_cp(sb + 3 * TILEB, pK0 + 64, 3072, tid);
    tile_cp(sb + 4 * TILEB, pV0,      3072, tid);
    tile_cp(sb + 5 * TILEB, pV0 + 64, 3072, tid);
    cp_commit();

    float oacc[16][4];
    #pragma unroll
    for (int i = 0; i < 16; i++)
        #pragma unroll
        for (int c = 0; c < 4; c++) oacc[i][c] = 0.0f;
    float mprev[2] = {-1e30f, -1e30f};
    float lsum[2]  = {0.0f, 0.0f};

    const int ar = l & 15, asel = l >> 4;
    const int br = ((l >> 4) << 3) + (l & 7), bsel = (l >> 3) & 1;
    const int sw = l & 7;
    const int vkr = ((l >> 3) & 1) * 8 + (l & 7);   // trans-V key-row
    const int vcg = l >> 4;                          // trans-V d col-group
    const float alpha = 0.08838834764831845f;        // 1/sqrt(128)

    for (int j = 0; j < 4; j++) {
        const int buf = j & 1;
        if (j < 3) {
            const int nb_ = buf ^ 1;
            const f16* pK = pK0 + (long)(j + 1) * 128 * 3072;
            const f16* pV = pV0 + (long)(j + 1) * 128 * 3072;
            tile_cp(sb + (2 + nb_ * 4 + 0) * TILEB, pK,      3072, tid);
            tile_cp(sb + (2 + nb_ * 4 + 1) * TILEB, pK + 64, 3072, tid);
            tile_cp(sb + (2 + nb_ * 4 + 2) * TILEB, pV,      3072, tid);
            tile_cp(sb + (2 + nb_ * 4 + 3) * TILEB, pV + 64, 3072, tid);
            cp_commit();
            cp_wait<1>();
        } else {
            cp_wait<0>();
        }
        __syncthreads();

        const uint32_t sK = sb + (2 + buf * 4) * TILEB;
        const uint32_t sV = sK + 2 * TILEB;

        float sacc[16][4];
        #pragma unroll
        for (int i = 0; i < 16; i++)
            #pragma unroll
            for (int c = 0; c < 4; c++) sacc[i][c] = 0.0f;

        #pragma unroll
        for (int kp = 0; kp < 8; kp++) {
            uint32_t aq[4];
            uint32_t qa = sb + (kp >> 2) * TILEB + (w * 16 + ar) * 128
                        + ((((kp & 3) * 2 + asel) ^ sw) << 4);
            ldsm4(aq[0], aq[1], aq[2], aq[3], qa);
            #pragma unroll
            for (int nb = 0; nb < 8; nb++) {
                uint32_t b0, b1, b2, b3;
                uint32_t ka = sK + (kp >> 2) * TILEB + (nb * 16 + br) * 128
                            + ((((kp & 3) * 2 + bsel) ^ sw) << 4);
                ldsm4(b0, b1, b2, b3, ka);
                mma16816(sacc[nb * 2],     aq, b0, b1);
                mma16816(sacc[nb * 2 + 1], aq, b2, b3);
            }
        }

        #pragma unroll
        for (int i = 0; i < 16; i++)
            #pragma unroll
            for (int c = 0; c < 4; c++) sacc[i][c] *= alpha;
        if (by == j) {
            int r0 = w * 16 + (l >> 2);
            #pragma unroll
            for (int nt = 0; nt < 16; nt++) {
                int cb = nt * 8 + (l & 3) * 2;
                if (cb     == r0)     sacc[nt][0] = 0.0f;
                if (cb + 1 == r0)     sacc[nt][1] = 0.0f;
                if (cb     == r0 + 8) sacc[nt][2] = 0.0f;
                if (cb + 1 == r0 + 8) sacc[nt][3] = 0.0f;
            }
        }

        #pragma unroll
        for (int g = 0; g < 2; g++) {
            float mx = -1e30f;
            #pragma unroll
            for (int nt = 0; nt < 16; nt++)
                mx = fmaxf(mx, fmaxf(sacc[nt][2 * g], sacc[nt][2 * g + 1]));
            mx = fmaxf(mx, __shfl_xor_sync(0xffffffffu, mx, 1));
            mx = fmaxf(mx, __shfl_xor_sync(0xffffffffu, mx, 2));
            float mnew = fmaxf(mprev[g], mx);
            float sc = __expf(mprev[g] - mnew);
            float sum = 0.0f;
            #pragma unroll
            for (int nt = 0; nt < 16; nt++) {
                float e0 = __expf(sacc[nt][2 * g]     - mnew);
                float e1 = __expf(sacc[nt][2 * g + 1] - mnew);
                sacc[nt][2 * g] = e0; sacc[nt][2 * g + 1] = e1;
                sum += e0 + e1;
            }
            sum += __shfl_xor_sync(0xffffffffu, sum, 1);
            sum += __shfl_xor_sync(0xffffffffu, sum, 2);
            lsum[g] = lsum[g] * sc + sum;
            mprev[g] = mnew;
            #pragma unroll
            for (int nt = 0; nt < 16; nt++) {
                oacc[nt][2 * g]     *= sc;
                oacc[nt][2 * g + 1] *= sc;
            }
        }

        uint32_t aP[8][4];
        #pragma unroll
        for (int t = 0; t < 8; t++) {
            aP[t][0] = f2h2(sacc[2*t][0],   sacc[2*t][1]);
            aP[t][1] = f2h2(sacc[2*t][2],   sacc[2*t][3]);
            aP[t][2] = f2h2(sacc[2*t+1][0], sacc[2*t+1][1]);
            aP[t][3] = f2h2(sacc[2*t+1][2], sacc[2*t+1][3]);
        }

        #pragma unroll
        for (int t = 0; t < 8; t++) {
            int vrow = t * 16 + vkr;
            #pragma unroll
            for (int nb = 0; nb < 8; nb++) {
                uint32_t b0, b1, b2, b3;
                uint32_t va = sV + (nb >> 2) * TILEB + vrow * 128
                            + (((((nb & 3) * 2) + vcg) ^ (vrow & 7)) << 4);
                ldsm4t(b0, b1, b2, b3, va);
                mma16816(oacc[nb * 2],     aP[t], b0, b1);
                mma16816(oacc[nb * 2 + 1], aP[t], b2, b3);
            }
        }
        __syncthreads();   // required: buffer distance is 1 in this pipeline
    }

    #pragma unroll
    for (int g = 0; g < 2; g++) {
        float inv = 1.0f / lsum[g];
        long m = qrow0 + w * 16 + (l >> 2) + 8 * g;
        f16* op = outp + m * Hc + h * HDc + (l & 3) * 2;
        #pragma unroll
        for (int nt = 0; nt < 16; nt++) {
            float v0 = oacc[nt][2 * g] * inv, v1 = oacc[nt][2 * g + 1] * inv;
            *(__half2*)(op + nt * 8) = __halves2half2(__float2half(v0), __float2half(v1));
        }
    }
}

// ---------------------------------------------------------------------------
// Launch
// ---------------------------------------------------------------------------
extern "C" void kernel_launch(void* const* d_in, const int* in_sizes, int n_in,
                              void* d_out, int out_size)
{
    const float* x      = (const float*)d_in[0];
    const float* conv_w = (const float*)d_in[1];
    const float* conv_b = (const float*)d_in[2];
    const float* w1 = (const float*)d_in[3];
    const float* b1 = (const float*)d_in[4];
    const float* w2 = (const float*)d_in[5];
    const float* b2 = (const float*)d_in[6];
    const float* ln_g = (const float*)d_in[7];
    const float* ln_b = (const float*)d_in[8];
    const float* wq = (const float*)d_in[9];
    const float* bq = (const float*)d_in[10];
    const float* wk = (const float*)d_in[11];
    const float* bk = (const float*)d_in[12];
    const float* wv = (const float*)d_in[13];
    const float* bv = (const float*)d_in[14];
    const float* wo = (const float*)d_in[15];
    const float* bo = (const float*)d_in[16];
    const float* wp = (const float*)d_in[17];
    const float* bp = (const float*)d_in[18];
    float* out = (float*)d_out;

    #define SYM(p, s) void* p; cudaGetSymbolAddress(&p, s)
    SYM(xah, g_xah);
    SYM(h1, g_h1);
    SYM(xreg, g_xreg);
    SYM(xnh, g_xnh);
    SYM(qkv, g_qkv);
    SYM(ch, g_ch);
    SYM(w1t, g_w1t); SYM(w2t, g_w2t);
    SYM(wqkv, g_wqkv); SYM(bqkv, g_bqkv);
    SYM(wo16, g_wo16); SYM(wpt, g_wpt); SYM(wopT, g_wopT); SYM(bop, g_bop);
    #undef SYM

    const int SMB_1 = NST * 2 * TILEB;   //  98304
    const int SMB_F = 10 * TILEB;        // 163840
    cudaFuncSetAttribute(mmk<1,3>, cudaFuncAttributeMaxDynamicSharedMemorySize, SMB_1);
    cudaFuncSetAttribute(mmk<0,1>, cudaFuncAttributeMaxDynamicSharedMemorySize, SMB_1);
    cudaFuncSetAttribute(mmk<1,1>, cudaFuncAttributeMaxDynamicSharedMemorySize, SMB_1);
    cudaFuncSetAttribute(mmk<1,0>, cudaFuncAttributeMaxDynamicSharedMemorySize, SMB_1);
    cudaFuncSetAttribute(mmk<0,5>, cudaFuncAttributeMaxDynamicSharedMemorySize, SMB_1);
    cudaFuncSetAttribute(fattn, cudaFuncAttributeMaxDynamicSharedMemorySize, SMB_F);

    const int BMrows = Bc * Mc;  // 32768

    // 1. conv means, affine -> fp16
    means_k<<<1, 1024>>>(conv_w, conv_b);
    affine_k<<<(unsigned)(BMM / 4 / 256), 256>>>((const float4*)x, (f16*)xah);

    // 2. weight prep: batched transpose + merged cast/bias kernel
    wsplit_all<<<dim3(32, 32, 6), dim3(32, 8)>>>(
        w1, w2, wq, wk, wv, wp, (f16*)w1t, (f16*)w2t, (f16*)wqkv, (f16*)wpt);
    prep_k<<<1040, 256>>>((const float4*)wo, (f16*)wo16,
                          bq, bk, bv, (float*)bqkv,
                          bo, wp, bp, (float*)bop);

    // 3. wopT[n,j] = sum_k wp[k,n]·wo[j,k] = (wo@wp)^T  -> [N,K] for final GEMM
    mmk<1,0><<<dim3(Hc/128, Hc/128, 1), 256, SMB_1>>>(
        (f16*)wpt, (f16*)wo16, nullptr, nullptr, nullptr, (f16*)wopT,
        Hc, Hc, Hc, Hc, 1, 0,0,0,0,0,0, 1.0f);

    // 4. h1 = relu(xa @ w1 + b1) -> fp16
    mmk<1,3><<<dim3(Hc/128, BMrows/128, 1), 256, SMB_1>>>(
        (f16*)xah, (f16*)w1t, b1, nullptr, nullptr, (f16*)h1,
        Mc, Mc, Mc, Hc, 1, 0,0,0,0,0,0, 1.0f);

    // 5. xreg = h1 @ w2 + b2 (fp32)
    mmk<0,1><<<dim3(Hc/128, BMrows/128, 1), 256, SMB_1>>>(
        (f16*)h1, (f16*)w2t, b2, nullptr, (float*)xreg, nullptr,
        Hc, Hc, Hc, Hc, 1, 0,0,0,0,0,0, 1.0f);

    // 6. layernorm -> fp16
    ln_k<<<BMrows, 256>>>((const float*)xreg, ln_g, ln_b, (f16*)xnh);

    // 7. fused q|k|v projection
    mmk<1,1><<<dim3(3*Hc/128, BMrows/128, 1), 256, SMB_1>>>(
        (f16*)xnh, (f16*)wqkv, (const float*)bqkv, nullptr, nullptr, (f16*)qkv,
        Hc, Hc, Hc, 3*Hc, 1, 0,0,0,0,0,0, 1.0f);

    // 8. fused attention (direct V, no transpose pass) -> ch
    fattn<<<dim3(Mc/128, Bc*NHc), 256, SMB_F>>>((const f16*)qkv, (f16*)ch);

    // 9. out = ctx @ (wo@wp) + (bo@wp + bp) + xreg (fp32)
    mmk<0,5><<<dim3(Hc/128, BMrows/128, 1), 256, SMB_1>>>(
        (f16*)ch, (f16*)wopT, (const float*)bop, (const float*)xreg, out, nullptr,
        Hc, Hc, Hc, Hc, 1, 0,0,0,0,0,0, 1.0f);
}